// round 2
// baseline (speedup 1.0000x reference)
#include <cuda_runtime.h>
#include <math.h>
#include <stdint.h>

// ---------------- problem constants ----------------
#define NBATCH   2
#define NPROP    512
#define NROI     1024            // B * N_PROP
#define CFEAT    256
#define FHW      200
#define PLANE    (FHW*FHW)       // 40000
#define POOLN    7
#define INDIM    (CFEAT*POOLN*POOLN)  // 12544
#define FCDIM    1024
#define NCLS     81
#define NSC      (NPROP*(NCLS-1))    // 40960 per batch
#define NSORT    65536
#define PRENMS   2048
#define NDETS    100
#define CLIPV    4.1351666f      // log(1000/16) rounded to f32

// ---------------- scratch (device globals; no runtime allocs) ----------------
__device__ float g_X[NROI*INDIM];        // pooled features, 51.4MB
__device__ float g_H1[NROI*FCDIM];
__device__ float g_H2[NROI*FCDIM];
__device__ float g_logits[NROI*NCLS];
__device__ float g_probs[NROI*NCLS];
__device__ float g_deltas[NROI*4];
__device__ float g_cur[NROI*4];
__device__ unsigned long long g_keys[NBATCH*NSORT];
__device__ float g_selbox[NBATCH*PRENMS*4];
__device__ float g_selval[NBATCH*PRENMS];
__device__ int   g_sellab[NBATCH*PRENMS];
__device__ int   g_Mv[NBATCH];

// ---------------- utility kernels ----------------
__global__ void zero_out_kernel(float* out, int n) {
    int i = blockIdx.x*blockDim.x + threadIdx.x;
    if (i < n) out[i] = 0.0f;
}
__global__ void copy_kernel(const float* __restrict__ src, float* __restrict__ dst, int n) {
    int i = blockIdx.x*blockDim.x + threadIdx.x;
    if (i < n) dst[i] = src[i];
}

// ---------------- RoI align ----------------
// one block per roi; 512 threads cover 256ch x 49 cells
__global__ void roi_align_kernel(const float* __restrict__ feat,
                                 const float* __restrict__ boxes,
                                 float* __restrict__ X)
{
    int r = blockIdx.x;
    int tid = threadIdx.x;
    __shared__ int   soff[4][196];
    __shared__ float sw  [4][196];
    if (tid < 196) {
        float x1 = boxes[r*4+0]*0.25f, y1 = boxes[r*4+1]*0.25f;
        float x2 = boxes[r*4+2]*0.25f, y2 = boxes[r*4+3]*0.25f;
        float bw = fmaxf(x2-x1, 1.0f) * (1.0f/7.0f);
        float bh = fmaxf(y2-y1, 1.0f) * (1.0f/7.0f);
        int cell = tid >> 2, s = tid & 3;
        int py = cell / 7, px = cell % 7;
        float sy = 0.25f + 0.5f*(float)(s >> 1);
        float sx = 0.25f + 0.5f*(float)(s & 1);
        float y = y1 + ((float)py + sy)*bh;
        float x = x1 + ((float)px + sx)*bw;
        float valid = (y > -1.0f && y < 200.0f && x > -1.0f && x < 200.0f) ? 1.0f : 0.0f;
        y = fminf(fmaxf(y, 0.0f), 199.0f);
        x = fminf(fmaxf(x, 0.0f), 199.0f);
        int y0 = (int)floorf(y), x0 = (int)floorf(x);
        int y1i = min(y0+1, 199), x1i = min(x0+1, 199);
        float ly = y - (float)y0, lx = x - (float)x0;
        float hy = 1.0f - ly, hx = 1.0f - lx;
        soff[0][tid] = y0 *FHW + x0;  sw[0][tid] = hy*hx*valid;
        soff[1][tid] = y0 *FHW + x1i; sw[1][tid] = hy*lx*valid;
        soff[2][tid] = y1i*FHW + x0;  sw[2][tid] = ly*hx*valid;
        soff[3][tid] = y1i*FHW + x1i; sw[3][tid] = ly*lx*valid;
    }
    __syncthreads();
    int b = r >> 9;
    const float* fb = feat + (size_t)b*CFEAT*PLANE;
    float* xr = X + (size_t)r*INDIM;
    for (int flat = tid; flat < INDIM; flat += blockDim.x) {
        int c = flat / 49, cell = flat % 49;
        const float* fp = fb + (size_t)c*PLANE;
        float acc = 0.0f;
        #pragma unroll
        for (int s = 0; s < 4; s++) {
            int e = cell*4 + s;
            acc += sw[0][e]*fp[soff[0][e]] + sw[1][e]*fp[soff[1][e]]
                 + sw[2][e]*fp[soff[2][e]] + sw[3][e]*fp[soff[3][e]];
        }
        xr[flat] = acc * 0.25f;
    }
}

// ---------------- 64x64x16 SGEMM, bias + optional relu ----------------
// C[M,N] = A[M,K] @ B[K,N] + bias ; 256 threads, TM=TN=4
__global__ void __launch_bounds__(256)
sgemm_bias_relu(const float* __restrict__ A, const float* __restrict__ Bw,
                const float* __restrict__ bias, float* __restrict__ C,
                int M, int N, int K, int doRelu)
{
    __shared__ float As[16][64];
    __shared__ float Bs[16][64];
    int tid = threadIdx.x;
    int bm = blockIdx.y * 64, bn = blockIdx.x * 64;
    int arow = tid >> 2, acol = (tid & 3) << 2;
    int brow = tid >> 4, bcol = (tid & 15) << 2;
    const float* Ap = A + (size_t)(bm + arow)*K + acol;
    const float* Bp = Bw + (size_t)brow*N + bn + bcol;
    int ty = tid >> 4, tx = tid & 15;
    float acc[4][4] = {};
    for (int k0 = 0; k0 < K; k0 += 16) {
        float4 av = *(const float4*)(Ap + k0);
        float4 bv = *(const float4*)(Bp + (size_t)k0*N);
        As[acol+0][arow] = av.x; As[acol+1][arow] = av.y;
        As[acol+2][arow] = av.z; As[acol+3][arow] = av.w;
        *(float4*)&Bs[brow][bcol] = bv;
        __syncthreads();
        #pragma unroll
        for (int kk = 0; kk < 16; kk++) {
            float4 a = *(const float4*)&As[kk][ty<<2];
            float4 b = *(const float4*)&Bs[kk][tx<<2];
            acc[0][0] += a.x*b.x; acc[0][1] += a.x*b.y; acc[0][2] += a.x*b.z; acc[0][3] += a.x*b.w;
            acc[1][0] += a.y*b.x; acc[1][1] += a.y*b.y; acc[1][2] += a.y*b.z; acc[1][3] += a.y*b.w;
            acc[2][0] += a.z*b.x; acc[2][1] += a.z*b.y; acc[2][2] += a.z*b.z; acc[2][3] += a.z*b.w;
            acc[3][0] += a.w*b.x; acc[3][1] += a.w*b.y; acc[3][2] += a.w*b.z; acc[3][3] += a.w*b.w;
        }
        __syncthreads();
    }
    float4 b4 = *(const float4*)(bias + bn + (tx<<2));
    float bj[4] = {b4.x, b4.y, b4.z, b4.w};
    #pragma unroll
    for (int ii = 0; ii < 4; ii++) {
        int row = bm + (ty<<2) + ii;
        float4 v;
        float* vv = (float*)&v;
        #pragma unroll
        for (int jj = 0; jj < 4; jj++) {
            float t = acc[ii][jj] + bj[jj];
            vv[jj] = doRelu ? fmaxf(t, 0.0f) : t;
        }
        *(float4*)(C + (size_t)row*N + bn + (tx<<2)) = v;
    }
}

// ---------------- logits head: [1024,1024] @ [1024,81] + bc ----------------
__global__ void __launch_bounds__(128)
gemm_logits(const float* __restrict__ H, const float* __restrict__ Wc,
            const float* __restrict__ bc, float* __restrict__ out)
{
    __shared__ float hs[4*1024];
    int m0 = blockIdx.x * 4;
    int t = threadIdx.x;
    const float4* src = (const float4*)(H + (size_t)m0*FCDIM);
    float4* dst = (float4*)hs;
    #pragma unroll
    for (int q = 0; q < 8; q++) dst[q*128 + t] = src[q*128 + t];
    __syncthreads();
    if (t < NCLS) {
        float a0=0, a1=0, a2=0, a3=0;
        for (int k = 0; k < FCDIM; k++) {
            float wv = Wc[k*NCLS + t];
            a0 += hs[k]*wv; a1 += hs[1024+k]*wv; a2 += hs[2048+k]*wv; a3 += hs[3072+k]*wv;
        }
        float bb = bc[t];
        out[(m0+0)*NCLS + t] = a0 + bb;
        out[(m0+1)*NCLS + t] = a1 + bb;
        out[(m0+2)*NCLS + t] = a2 + bb;
        out[(m0+3)*NCLS + t] = a3 + bb;
    }
}

// ---------------- delta head: [1024,1024] @ [1024,4] + br ----------------
__global__ void __launch_bounds__(64)
gemm_deltas(const float* __restrict__ H, const float* __restrict__ Wr,
            const float* __restrict__ br, float* __restrict__ out)
{
    int t = threadIdx.x;            // 64 threads: 16 rows x 4 cols
    int m0 = blockIdx.x * 16;
    int r = t >> 2, n = t & 3;
    int row = m0 + r;
    const float* hp = H + (size_t)row*FCDIM;
    float a0=0, a1=0, a2=0, a3=0;
    for (int k = 0; k < FCDIM; k += 4) {
        a0 += hp[k+0]*Wr[(k+0)*4+n];
        a1 += hp[k+1]*Wr[(k+1)*4+n];
        a2 += hp[k+2]*Wr[(k+2)*4+n];
        a3 += hp[k+3]*Wr[(k+3)*4+n];
    }
    out[row*4+n] = (a0+a1)+(a2+a3) + br[n];
}

// ---------------- box decode (in-place on g_cur) ----------------
__global__ void decode_kernel(float* __restrict__ cur, const float* __restrict__ deltas,
                              float wx, float wy, float ww, float wh)
{
    int i = blockIdx.x*blockDim.x + threadIdx.x;
    if (i >= NROI) return;
    float px1 = cur[i*4+0], py1 = cur[i*4+1], px2 = cur[i*4+2], py2 = cur[i*4+3];
    float pw = fmaxf(px2 - px1, 1e-6f);
    float ph = fmaxf(py2 - py1, 1e-6f);
    float px = px1 + 0.5f*pw, py = py1 + 0.5f*ph;
    float dx = deltas[i*4+0]*wx, dy = deltas[i*4+1]*wy;
    float dw = fminf(deltas[i*4+2]*ww, CLIPV);
    float dh = fminf(deltas[i*4+3]*wh, CLIPV);
    float gx = dx*pw + px, gy = dy*ph + py;
    float gw = expf(dw)*pw, gh = expf(dh)*ph;
    cur[i*4+0] = fminf(fmaxf(gx - 0.5f*gw, 0.0f), 800.0f);
    cur[i*4+1] = fminf(fmaxf(gy - 0.5f*gh, 0.0f), 800.0f);
    cur[i*4+2] = fminf(fmaxf(gx + 0.5f*gw, 0.0f), 800.0f);
    cur[i*4+3] = fminf(fmaxf(gy + 0.5f*gh, 0.0f), 800.0f);
}

// ---------------- softmax over 81 classes ----------------
__global__ void __launch_bounds__(128)
softmax81(const float* __restrict__ logits, float* __restrict__ probs)
{
    int m = blockIdx.x, t = threadIdx.x;
    __shared__ float red[128];
    float v = (t < NCLS) ? logits[m*NCLS + t] : -3.0e38f;
    red[t] = v; __syncthreads();
    for (int s = 64; s > 0; s >>= 1) { if (t < s) red[t] = fmaxf(red[t], red[t+s]); __syncthreads(); }
    float mx = red[0];
    __syncthreads();
    float e = (t < NCLS) ? expf(v - mx) : 0.0f;
    red[t] = e; __syncthreads();
    for (int s = 64; s > 0; s >>= 1) { if (t < s) red[t] += red[t+s]; __syncthreads(); }
    float sum = red[0];
    if (t < NCLS) probs[m*NCLS + t] = e / sum;
}

// ---------------- sort keys: (sortable score << 32) | (~idx) ----------------
__global__ void build_keys(const float* __restrict__ probs, const float* __restrict__ boxes,
                           unsigned long long* __restrict__ keys, int* __restrict__ Mv)
{
    int t = blockIdx.x*blockDim.x + threadIdx.x;
    if (t == 0) { Mv[0] = 0; Mv[1] = 0; }
    if (t >= NBATCH*NSORT) return;
    int b = t >> 16, i = t & (NSORT-1);
    unsigned long long key = 0ull;
    if (i < NSC) {
        int roi = i / (NCLS-1);
        int cls = (i % (NCLS-1)) + 1;
        const float* bp = boxes + ((size_t)b*NPROP + roi)*4;
        float ws = bp[2] - bp[0], hs = bp[3] - bp[1];
        float fg = probs[((size_t)b*NPROP + roi)*NCLS + cls];
        unsigned int sb;
        if (fg > 0.05f && ws >= 1.0f && hs >= 1.0f) {
            sb = __float_as_uint(fg) | 0x80000000u;      // positive float -> sortable
        } else {
            sb = 0x407FFFFFu;                            // sortable(-1.0f)
        }
        key = ((unsigned long long)sb << 32) | (unsigned long long)(0xFFFFFFFFu - (unsigned int)i);
    }
    keys[t] = key;
}

// ---------------- bitonic sort (descending), n=65536 per batch ----------------
__device__ __forceinline__ void cmp_swap_desc(unsigned long long& x, unsigned long long& y, bool up) {
    // "up" segment of an ascending network -> for DESCENDING final sort, swap if x < y
    if (up ? (x < y) : (x > y)) { unsigned long long t = x; x = y; y = t; }
}

__global__ void __launch_bounds__(1024)
bitonic_local_full(unsigned long long* __restrict__ keys)
{
    __shared__ unsigned long long sk[2048];
    int chunk = blockIdx.x, b = blockIdx.y;
    unsigned long long* g = keys + (size_t)b*NSORT + (size_t)chunk*2048;
    int base = chunk*2048;
    int tid = threadIdx.x;
    sk[tid] = g[tid]; sk[tid+1024] = g[tid+1024];
    __syncthreads();
    for (int k = 2; k <= 2048; k <<= 1) {
        for (int j = k >> 1; j >= 1; j >>= 1) {
            int i = ((tid & ~(j-1)) << 1) | (tid & (j-1));
            int l = i + j;
            bool up = (((base + i) & k) == 0);
            unsigned long long x = sk[i], y = sk[l];
            if (up ? (x < y) : (x > y)) { sk[i] = y; sk[l] = x; }
            __syncthreads();
        }
    }
    g[tid] = sk[tid]; g[tid+1024] = sk[tid+1024];
}

__global__ void __launch_bounds__(1024)
bitonic_local_finish(unsigned long long* __restrict__ keys, int k)
{
    __shared__ unsigned long long sk[2048];
    int chunk = blockIdx.x, b = blockIdx.y;
    unsigned long long* g = keys + (size_t)b*NSORT + (size_t)chunk*2048;
    int base = chunk*2048;
    int tid = threadIdx.x;
    sk[tid] = g[tid]; sk[tid+1024] = g[tid+1024];
    __syncthreads();
    for (int j = 1024; j >= 1; j >>= 1) {
        int i = ((tid & ~(j-1)) << 1) | (tid & (j-1));
        int l = i + j;
        bool up = (((base + i) & k) == 0);
        unsigned long long x = sk[i], y = sk[l];
        if (up ? (x < y) : (x > y)) { sk[i] = y; sk[l] = x; }
        __syncthreads();
    }
    g[tid] = sk[tid]; g[tid+1024] = sk[tid+1024];
}

__global__ void __launch_bounds__(256)
bitonic_global(unsigned long long* __restrict__ keys, int k, int j)
{
    int t = blockIdx.x*blockDim.x + threadIdx.x;   // [0, 32768) pairs
    int b = blockIdx.y;
    unsigned long long* g = keys + (size_t)b*NSORT;
    int i = ((t & ~(j-1)) << 1) | (t & (j-1));
    int l = i + j;
    bool up = ((i & k) == 0);
    unsigned long long x = g[i], y = g[l];
    if (up ? (x < y) : (x > y)) { g[i] = y; g[l] = x; }
}

// ---------------- extract top-2048 per batch ----------------
__global__ void extract_topk(const unsigned long long* __restrict__ keys,
                             const float* __restrict__ boxes,
                             float* __restrict__ selbox, float* __restrict__ selval,
                             int* __restrict__ sellab, int* __restrict__ Mv)
{
    int t = blockIdx.x*blockDim.x + threadIdx.x;
    if (t >= NBATCH*PRENMS) return;
    int b = t >> 11, r = t & (PRENMS-1);
    unsigned long long key = keys[(size_t)b*NSORT + r];
    unsigned int sb = (unsigned int)(key >> 32);
    unsigned int lo = (unsigned int)key;
    float4 bx = make_float4(0,0,0,0);
    int lab = 0; float val = 0.0f;
    if (sb > 0x80000000u) {   // score > 0 (i.e., passed threshold)
        unsigned int idx = 0xFFFFFFFFu - lo;
        int roi = idx / (NCLS-1);
        int cls = idx % (NCLS-1) + 1;
        const float* bp = boxes + ((size_t)b*NPROP + roi)*4;
        bx = make_float4(bp[0], bp[1], bp[2], bp[3]);
        lab = cls;
        val = __uint_as_float(sb & 0x7FFFFFFFu);
        atomicAdd(&Mv[b], 1);
    }
    ((float4*)selbox)[b*PRENMS + r] = bx;
    sellab[b*PRENMS + r] = lab;
    selval[b*PRENMS + r] = val;
}

// ---------------- greedy NMS + output packing (one block per batch) ----------------
__global__ void __launch_bounds__(1024)
nms_output(const float* __restrict__ selbox, const float* __restrict__ selval,
           const int* __restrict__ sellab, const int* __restrict__ Mv,
           float* __restrict__ out)
{
    int b = blockIdx.x;
    int tid = threadIdx.x;
    __shared__ float4 sbox[PRENMS];
    __shared__ int    slab[PRENMS];
    __shared__ unsigned char skeep[PRENMS];
    __shared__ int soutidx[NDETS];
    __shared__ int sK;
    int lim = Mv[b]; if (lim > PRENMS) lim = PRENMS;
    for (int r = tid; r < PRENMS; r += 1024) {
        sbox[r] = ((const float4*)selbox)[b*PRENMS + r];
        slab[r] = sellab[b*PRENMS + r];
        skeep[r] = (r < lim) ? 1 : 0;
    }
    __syncthreads();
    for (int i = 0; i < lim; i++) {
        if (skeep[i]) {
            float4 bi = sbox[i]; int li = slab[i];
            float areaI = (bi.z - bi.x)*(bi.w - bi.y);
            for (int j = i + 1 + tid; j < lim; j += 1024) {
                if (skeep[j] && slab[j] == li) {
                    float4 bj = sbox[j];
                    float ix = fminf(bi.z, bj.z) - fmaxf(bi.x, bj.x);
                    float iy = fminf(bi.w, bj.w) - fmaxf(bi.y, bj.y);
                    float inter = fmaxf(ix, 0.0f)*fmaxf(iy, 0.0f);
                    float areaJ = (bj.z - bj.x)*(bj.w - bj.y);
                    float iou = inter / (areaI + areaJ - inter + 1e-12f);
                    if (iou > 0.5f) skeep[j] = 0;
                }
            }
        }
        __syncthreads();
    }
    if (tid == 0) {
        int k = 0;
        for (int r = 0; r < lim && k < NDETS; r++)
            if (skeep[r]) soutidx[k++] = r;
        sK = k;
    }
    __syncthreads();
    if (tid < NDETS) {
        float x0=0, y0=0, x1=0, y1=0, sc=0, lb=0;
        if (tid < sK) {
            int r = soutidx[tid];
            float4 bb = sbox[r];
            x0 = bb.x; y0 = bb.y; x1 = bb.z; y1 = bb.w;
            sc = selval[b*PRENMS + r];
            lb = (float)slab[r];
        }
        float* ob = out + (size_t)b*NDETS*4 + tid*4;
        ob[0] = x0; ob[1] = y0; ob[2] = x1; ob[3] = y1;
        out[NBATCH*NDETS*4 + b*NDETS + tid] = sc;                 // scores at 800
        out[NBATCH*NDETS*4 + NBATCH*NDETS + b*NDETS + tid] = lb;  // labels at 1000
    }
}

// ---------------- host launch ----------------
extern "C" void kernel_launch(void* const* d_in, const int* in_sizes, int n_in,
                              void* d_out, int out_size)
{
    const float* features  = (const float*)d_in[0];
    const float* proposals = (const float*)d_in[1];
    const float* W1 = (const float*)d_in[2];
    const float* b1 = (const float*)d_in[3];
    const float* W2 = (const float*)d_in[4];
    const float* b2 = (const float*)d_in[5];
    const float* Wc = (const float*)d_in[6];
    const float* bc = (const float*)d_in[7];
    const float* Wr = (const float*)d_in[8];
    const float* br = (const float*)d_in[9];
    float* out = (float*)d_out;

    // resolve scratch symbol addresses (pure address queries; graph-safe)
    float *pX, *pH1, *pH2, *pLg, *pPr, *pDl, *pCur, *pSelB, *pSelV;
    unsigned long long* pKeys; int *pSelL, *pMv;
    cudaGetSymbolAddress((void**)&pX,   g_X);
    cudaGetSymbolAddress((void**)&pH1,  g_H1);
    cudaGetSymbolAddress((void**)&pH2,  g_H2);
    cudaGetSymbolAddress((void**)&pLg,  g_logits);
    cudaGetSymbolAddress((void**)&pPr,  g_probs);
    cudaGetSymbolAddress((void**)&pDl,  g_deltas);
    cudaGetSymbolAddress((void**)&pCur, g_cur);
    cudaGetSymbolAddress((void**)&pKeys,g_keys);
    cudaGetSymbolAddress((void**)&pSelB,g_selbox);
    cudaGetSymbolAddress((void**)&pSelV,g_selval);
    cudaGetSymbolAddress((void**)&pSelL,g_sellab);
    cudaGetSymbolAddress((void**)&pMv,  g_Mv);

    // zero output (covers any layout padding in d_out)
    zero_out_kernel<<<(out_size + 255)/256, 256>>>(out, out_size);

    // cur = proposals
    copy_kernel<<<(NROI*4 + 255)/256, 256>>>(proposals, pCur, NROI*4);

    const float stds[3][4] = {
        {0.1f, 0.1f, 0.2f, 0.2f},
        {0.05f, 0.05f, 0.1f, 0.1f},
        {0.033f, 0.033f, 0.067f, 0.067f}
    };

    for (int s = 0; s < 3; s++) {
        roi_align_kernel<<<NROI, 512>>>(features, pCur, pX);

        dim3 g1(FCDIM/64, NROI/64);   // (16,16)
        sgemm_bias_relu<<<g1, 256>>>(pX,  W1 + (size_t)s*INDIM*FCDIM, b1 + s*FCDIM,
                                     pH1, NROI, FCDIM, INDIM, 1);
        sgemm_bias_relu<<<g1, 256>>>(pH1, W2 + (size_t)s*FCDIM*FCDIM, b2 + s*FCDIM,
                                     pH2, NROI, FCDIM, FCDIM, 1);
        if (s == 2)
            gemm_logits<<<NROI/4, 128>>>(pH2, Wc + (size_t)s*FCDIM*NCLS, bc + s*NCLS, pLg);

        gemm_deltas<<<NROI/16, 64>>>(pH2, Wr + (size_t)s*FCDIM*4, br + s*4, pDl);
        decode_kernel<<<(NROI + 255)/256, 256>>>(pCur, pDl,
                                                 stds[s][0], stds[s][1], stds[s][2], stds[s][3]);
    }

    softmax81<<<NROI, 128>>>(pLg, pPr);
    build_keys<<<(NBATCH*NSORT + 255)/256, 256>>>(pPr, pCur, pKeys, pMv);

    // bitonic sort, descending, 65536 per batch
    dim3 gl(NSORT/2048, NBATCH);      // (32, 2) local blocks
    dim3 gg(NSORT/2/256, NBATCH);     // (128, 2) global step blocks
    bitonic_local_full<<<gl, 1024>>>(pKeys);
    for (int k = 4096; k <= NSORT; k <<= 1) {
        for (int j = k >> 1; j >= 2048; j >>= 1)
            bitonic_global<<<gg, 256>>>(pKeys, k, j);
        bitonic_local_finish<<<gl, 1024>>>(pKeys, k);
    }

    extract_topk<<<(NBATCH*PRENMS + 255)/256, 256>>>(pKeys, pCur, pSelB, pSelV, pSelL, pMv);
    nms_output<<<NBATCH, 1024>>>(pSelB, pSelV, pSelL, pMv, out);
}

// round 3
// speedup vs baseline: 1.0599x; 1.0599x over previous
#include <cuda_runtime.h>
#include <math.h>
#include <stdint.h>

// ---------------- problem constants ----------------
#define NBATCH   2
#define NPROP    512
#define NROI     1024            // B * N_PROP
#define CFEAT    256
#define FHW      200
#define PLANE    (FHW*FHW)       // 40000
#define POOLN    7
#define INDIM    (CFEAT*POOLN*POOLN)  // 12544
#define FCDIM    1024
#define NCLS     81
#define NSC      (NPROP*(NCLS-1))    // 40960 per batch
#define NSORT    65536
#define PRENMS   2048
#define NDETS    100
#define CLIPV    4.1351666f      // log(1000/16) rounded to f32

typedef unsigned long long ull;

// ---------------- scratch (device globals; no runtime allocs) ----------------
__device__ float g_X[NROI*INDIM];        // pooled features, 51.4MB
__device__ float g_H1[NROI*FCDIM];
__device__ float g_H2[NROI*FCDIM];
__device__ float g_logits[NROI*NCLS];
__device__ float g_probs[NROI*NCLS];
__device__ float g_deltas[NROI*4];
__device__ float g_cur[NROI*4];
__device__ unsigned long long g_keys[NBATCH*NSORT];
__device__ float g_selbox[NBATCH*PRENMS*4];
__device__ float g_selval[NBATCH*PRENMS];
__device__ int   g_sellab[NBATCH*PRENMS];
__device__ int   g_Mv[NBATCH];

// ---------------- f32x2 packed helpers (sm_100a) ----------------
__device__ __forceinline__ ull pack2(float x, float y) {
    ull r;
    asm("mov.b64 %0, {%1, %2};" : "=l"(r) : "f"(x), "f"(y));
    return r;
}
__device__ __forceinline__ void fma2(ull& d, ull a, ull b) {
    asm("fma.rn.f32x2 %0, %1, %2, %0;" : "+l"(d) : "l"(a), "l"(b));
}
__device__ __forceinline__ float2 unpack2(ull v) {
    float2 r;
    asm("mov.b64 {%0, %1}, %2;" : "=f"(r.x), "=f"(r.y) : "l"(v));
    return r;
}

// ---------------- utility kernels ----------------
__global__ void zero_out_kernel(float* out, int n) {
    int i = blockIdx.x*blockDim.x + threadIdx.x;
    if (i < n) out[i] = 0.0f;
}
__global__ void copy_kernel(const float* __restrict__ src, float* __restrict__ dst, int n) {
    int i = blockIdx.x*blockDim.x + threadIdx.x;
    if (i < n) dst[i] = src[i];
}

// ---------------- RoI align ----------------
// one block per roi; 512 threads cover 256ch x 49 cells
__global__ void roi_align_kernel(const float* __restrict__ feat,
                                 const float* __restrict__ boxes,
                                 float* __restrict__ X)
{
    int r = blockIdx.x;
    int tid = threadIdx.x;
    __shared__ int   soff[4][196];
    __shared__ float sw  [4][196];
    if (tid < 196) {
        float x1 = boxes[r*4+0]*0.25f, y1 = boxes[r*4+1]*0.25f;
        float x2 = boxes[r*4+2]*0.25f, y2 = boxes[r*4+3]*0.25f;
        float bw = fmaxf(x2-x1, 1.0f) * (1.0f/7.0f);
        float bh = fmaxf(y2-y1, 1.0f) * (1.0f/7.0f);
        int cell = tid >> 2, s = tid & 3;
        int py = cell / 7, px = cell % 7;
        float sy = 0.25f + 0.5f*(float)(s >> 1);
        float sx = 0.25f + 0.5f*(float)(s & 1);
        float y = y1 + ((float)py + sy)*bh;
        float x = x1 + ((float)px + sx)*bw;
        float valid = (y > -1.0f && y < 200.0f && x > -1.0f && x < 200.0f) ? 1.0f : 0.0f;
        y = fminf(fmaxf(y, 0.0f), 199.0f);
        x = fminf(fmaxf(x, 0.0f), 199.0f);
        int y0 = (int)floorf(y), x0 = (int)floorf(x);
        int y1i = min(y0+1, 199), x1i = min(x0+1, 199);
        float ly = y - (float)y0, lx = x - (float)x0;
        float hy = 1.0f - ly, hx = 1.0f - lx;
        soff[0][tid] = y0 *FHW + x0;  sw[0][tid] = hy*hx*valid;
        soff[1][tid] = y0 *FHW + x1i; sw[1][tid] = hy*lx*valid;
        soff[2][tid] = y1i*FHW + x0;  sw[2][tid] = ly*hx*valid;
        soff[3][tid] = y1i*FHW + x1i; sw[3][tid] = ly*lx*valid;
    }
    __syncthreads();
    int b = r >> 9;
    const float* fb = feat + (size_t)b*CFEAT*PLANE;
    float* xr = X + (size_t)r*INDIM;
    for (int flat = tid; flat < INDIM; flat += blockDim.x) {
        int c = flat / 49, cell = flat % 49;
        const float* fp = fb + (size_t)c*PLANE;
        float acc = 0.0f;
        #pragma unroll
        for (int s = 0; s < 4; s++) {
            int e = cell*4 + s;
            acc += sw[0][e]*fp[soff[0][e]] + sw[1][e]*fp[soff[1][e]]
                 + sw[2][e]*fp[soff[2][e]] + sw[3][e]*fp[soff[3][e]];
        }
        xr[flat] = acc * 0.25f;
    }
}

// ---------------- 128x64x16 SGEMM with f32x2, bias + optional relu ----------------
// C[M,N] = A[M,K] @ B[K,N] + bias ; 256 threads, per-thread 8(M)x4(N),
// accumulators packed as f32x2 pairs over M. Double-buffered smem.
#define BM 128
#define BN 64
#define BK 16

__global__ void __launch_bounds__(256)
sgemm_f32x2(const float* __restrict__ A, const float* __restrict__ Bw,
            const float* __restrict__ bias, float* __restrict__ C,
            int M, int N, int K, int doRelu)
{
    __shared__ __align__(16) float As[2][BK][BM];
    __shared__ __align__(16) float Bs[2][BK][BN];

    int tid = threadIdx.x;
    int bm = blockIdx.y * BM, bn = blockIdx.x * BN;

    // compute mapping: 16(tx over N) x 16(ty over M)
    int tx = tid & 15, ty = tid >> 4;
    int m0 = ty << 3;          // tile-local M base (8 rows)
    int n0 = tx << 2;          // tile-local N base (4 cols)

    // load mapping
    int arow = tid >> 2;             // 0..63, plus +64
    int akq  = (tid & 3) << 2;       // k offset 0,4,8,12
    int brow = tid >> 4;             // 0..15
    int bcol = (tid & 15) << 2;

    const float* Ap = A + (size_t)bm * K;
    const float* Bp = Bw + bn;

    ull acc[4][4];
    #pragma unroll
    for (int i = 0; i < 4; i++)
        #pragma unroll
        for (int j = 0; j < 4; j++) acc[i][j] = 0ull;

    int nK = K / BK;

    // prologue: load k-block 0 into regs, store to buf 0
    float4 ra0 = *(const float4*)(Ap + (size_t)arow*K + akq);
    float4 ra1 = *(const float4*)(Ap + (size_t)(arow+64)*K + akq);
    float4 rb  = *(const float4*)(Bp + (size_t)brow*N + bcol);
    As[0][akq+0][arow] = ra0.x; As[0][akq+1][arow] = ra0.y;
    As[0][akq+2][arow] = ra0.z; As[0][akq+3][arow] = ra0.w;
    As[0][akq+0][arow+64] = ra1.x; As[0][akq+1][arow+64] = ra1.y;
    As[0][akq+2][arow+64] = ra1.z; As[0][akq+3][arow+64] = ra1.w;
    *(float4*)&Bs[0][brow][bcol] = rb;
    __syncthreads();

    int buf = 0;
    for (int kb = 0; kb < nK; kb++) {
        // prefetch next k-block from global
        if (kb + 1 < nK) {
            int k0 = (kb + 1) * BK;
            ra0 = *(const float4*)(Ap + (size_t)arow*K + k0 + akq);
            ra1 = *(const float4*)(Ap + (size_t)(arow+64)*K + k0 + akq);
            rb  = *(const float4*)(Bp + (size_t)(k0 + brow)*N + bcol);
        }
        // compute BK k-steps from current buffer
        #pragma unroll
        for (int k = 0; k < BK; k++) {
            float4 af0 = *(const float4*)&As[buf][k][m0];
            float4 af1 = *(const float4*)&As[buf][k][m0+4];
            ull a2[4];
            a2[0] = ((const ull*)&af0)[0];   // rows m0, m0+1
            a2[1] = ((const ull*)&af0)[1];   // rows m0+2, m0+3
            a2[2] = ((const ull*)&af1)[0];
            a2[3] = ((const ull*)&af1)[1];
            float4 bf = *(const float4*)&Bs[buf][k][n0];
            ull b2[4];
            b2[0] = pack2(bf.x, bf.x);
            b2[1] = pack2(bf.y, bf.y);
            b2[2] = pack2(bf.z, bf.z);
            b2[3] = pack2(bf.w, bf.w);
            #pragma unroll
            for (int i = 0; i < 4; i++) {
                fma2(acc[i][0], a2[i], b2[0]);
                fma2(acc[i][1], a2[i], b2[1]);
                fma2(acc[i][2], a2[i], b2[2]);
                fma2(acc[i][3], a2[i], b2[3]);
            }
        }
        // stage next block into the other buffer
        if (kb + 1 < nK) {
            int nb = buf ^ 1;
            As[nb][akq+0][arow] = ra0.x; As[nb][akq+1][arow] = ra0.y;
            As[nb][akq+2][arow] = ra0.z; As[nb][akq+3][arow] = ra0.w;
            As[nb][akq+0][arow+64] = ra1.x; As[nb][akq+1][arow+64] = ra1.y;
            As[nb][akq+2][arow+64] = ra1.z; As[nb][akq+3][arow+64] = ra1.w;
            *(float4*)&Bs[nb][brow][bcol] = rb;
        }
        __syncthreads();
        buf ^= 1;
    }

    // epilogue
    float4 b4 = *(const float4*)(bias + bn + n0);
    #pragma unroll
    for (int i = 0; i < 4; i++) {
        float2 u0 = unpack2(acc[i][0]);
        float2 u1 = unpack2(acc[i][1]);
        float2 u2 = unpack2(acc[i][2]);
        float2 u3 = unpack2(acc[i][3]);
        float4 v0, v1;
        v0.x = u0.x + b4.x; v0.y = u1.x + b4.y; v0.z = u2.x + b4.z; v0.w = u3.x + b4.w;
        v1.x = u0.y + b4.x; v1.y = u1.y + b4.y; v1.z = u2.y + b4.z; v1.w = u3.y + b4.w;
        if (doRelu) {
            v0.x = fmaxf(v0.x, 0.f); v0.y = fmaxf(v0.y, 0.f);
            v0.z = fmaxf(v0.z, 0.f); v0.w = fmaxf(v0.w, 0.f);
            v1.x = fmaxf(v1.x, 0.f); v1.y = fmaxf(v1.y, 0.f);
            v1.z = fmaxf(v1.z, 0.f); v1.w = fmaxf(v1.w, 0.f);
        }
        int row0 = bm + m0 + 2*i;
        *(float4*)(C + (size_t)row0*N + bn + n0)     = v0;
        *(float4*)(C + (size_t)(row0+1)*N + bn + n0) = v1;
    }
}

// ---------------- logits head: [1024,1024] @ [1024,81] + bc ----------------
__global__ void __launch_bounds__(128)
gemm_logits(const float* __restrict__ H, const float* __restrict__ Wc,
            const float* __restrict__ bc, float* __restrict__ out)
{
    __shared__ float hs[4*1024];
    int m0 = blockIdx.x * 4;
    int t = threadIdx.x;
    const float4* src = (const float4*)(H + (size_t)m0*FCDIM);
    float4* dst = (float4*)hs;
    #pragma unroll
    for (int q = 0; q < 8; q++) dst[q*128 + t] = src[q*128 + t];
    __syncthreads();
    if (t < NCLS) {
        float a0=0, a1=0, a2=0, a3=0;
        for (int k = 0; k < FCDIM; k++) {
            float wv = Wc[k*NCLS + t];
            a0 += hs[k]*wv; a1 += hs[1024+k]*wv; a2 += hs[2048+k]*wv; a3 += hs[3072+k]*wv;
        }
        float bb = bc[t];
        out[(m0+0)*NCLS + t] = a0 + bb;
        out[(m0+1)*NCLS + t] = a1 + bb;
        out[(m0+2)*NCLS + t] = a2 + bb;
        out[(m0+3)*NCLS + t] = a3 + bb;
    }
}

// ---------------- delta head: [1024,1024] @ [1024,4] + br ----------------
__global__ void __launch_bounds__(64)
gemm_deltas(const float* __restrict__ H, const float* __restrict__ Wr,
            const float* __restrict__ br, float* __restrict__ out)
{
    int t = threadIdx.x;            // 64 threads: 16 rows x 4 cols
    int m0 = blockIdx.x * 16;
    int r = t >> 2, n = t & 3;
    int row = m0 + r;
    const float* hp = H + (size_t)row*FCDIM;
    float a0=0, a1=0, a2=0, a3=0;
    for (int k = 0; k < FCDIM; k += 4) {
        a0 += hp[k+0]*Wr[(k+0)*4+n];
        a1 += hp[k+1]*Wr[(k+1)*4+n];
        a2 += hp[k+2]*Wr[(k+2)*4+n];
        a3 += hp[k+3]*Wr[(k+3)*4+n];
    }
    out[row*4+n] = (a0+a1)+(a2+a3) + br[n];
}

// ---------------- box decode (in-place on g_cur) ----------------
__global__ void decode_kernel(float* __restrict__ cur, const float* __restrict__ deltas,
                              float wx, float wy, float ww, float wh)
{
    int i = blockIdx.x*blockDim.x + threadIdx.x;
    if (i >= NROI) return;
    float px1 = cur[i*4+0], py1 = cur[i*4+1], px2 = cur[i*4+2], py2 = cur[i*4+3];
    float pw = fmaxf(px2 - px1, 1e-6f);
    float ph = fmaxf(py2 - py1, 1e-6f);
    float px = px1 + 0.5f*pw, py = py1 + 0.5f*ph;
    float dx = deltas[i*4+0]*wx, dy = deltas[i*4+1]*wy;
    float dw = fminf(deltas[i*4+2]*ww, CLIPV);
    float dh = fminf(deltas[i*4+3]*wh, CLIPV);
    float gx = dx*pw + px, gy = dy*ph + py;
    float gw = expf(dw)*pw, gh = expf(dh)*ph;
    cur[i*4+0] = fminf(fmaxf(gx - 0.5f*gw, 0.0f), 800.0f);
    cur[i*4+1] = fminf(fmaxf(gy - 0.5f*gh, 0.0f), 800.0f);
    cur[i*4+2] = fminf(fmaxf(gx + 0.5f*gw, 0.0f), 800.0f);
    cur[i*4+3] = fminf(fmaxf(gy + 0.5f*gh, 0.0f), 800.0f);
}

// ---------------- softmax over 81 classes ----------------
__global__ void __launch_bounds__(128)
softmax81(const float* __restrict__ logits, float* __restrict__ probs)
{
    int m = blockIdx.x, t = threadIdx.x;
    __shared__ float red[128];
    float v = (t < NCLS) ? logits[m*NCLS + t] : -3.0e38f;
    red[t] = v; __syncthreads();
    for (int s = 64; s > 0; s >>= 1) { if (t < s) red[t] = fmaxf(red[t], red[t+s]); __syncthreads(); }
    float mx = red[0];
    __syncthreads();
    float e = (t < NCLS) ? expf(v - mx) : 0.0f;
    red[t] = e; __syncthreads();
    for (int s = 64; s > 0; s >>= 1) { if (t < s) red[t] += red[t+s]; __syncthreads(); }
    float sum = red[0];
    if (t < NCLS) probs[m*NCLS + t] = e / sum;
}

// ---------------- sort keys: (sortable score << 32) | (~idx) ----------------
__global__ void build_keys(const float* __restrict__ probs, const float* __restrict__ boxes,
                           unsigned long long* __restrict__ keys, int* __restrict__ Mv)
{
    int t = blockIdx.x*blockDim.x + threadIdx.x;
    if (t == 0) { Mv[0] = 0; Mv[1] = 0; }
    if (t >= NBATCH*NSORT) return;
    int b = t >> 16, i = t & (NSORT-1);
    unsigned long long key = 0ull;
    if (i < NSC) {
        int roi = i / (NCLS-1);
        int cls = (i % (NCLS-1)) + 1;
        const float* bp = boxes + ((size_t)b*NPROP + roi)*4;
        float ws = bp[2] - bp[0], hs = bp[3] - bp[1];
        float fg = probs[((size_t)b*NPROP + roi)*NCLS + cls];
        unsigned int sb;
        if (fg > 0.05f && ws >= 1.0f && hs >= 1.0f) {
            sb = __float_as_uint(fg) | 0x80000000u;      // positive float -> sortable
        } else {
            sb = 0x407FFFFFu;                            // sortable(-1.0f)
        }
        key = ((unsigned long long)sb << 32) | (unsigned long long)(0xFFFFFFFFu - (unsigned int)i);
    }
    keys[t] = key;
}

// ---------------- bitonic sort (descending), n=65536 per batch ----------------
__global__ void __launch_bounds__(1024)
bitonic_local_full(unsigned long long* __restrict__ keys)
{
    __shared__ unsigned long long sk[2048];
    int chunk = blockIdx.x, b = blockIdx.y;
    unsigned long long* g = keys + (size_t)b*NSORT + (size_t)chunk*2048;
    int base = chunk*2048;
    int tid = threadIdx.x;
    sk[tid] = g[tid]; sk[tid+1024] = g[tid+1024];
    __syncthreads();
    for (int k = 2; k <= 2048; k <<= 1) {
        for (int j = k >> 1; j >= 1; j >>= 1) {
            int i = ((tid & ~(j-1)) << 1) | (tid & (j-1));
            int l = i + j;
            bool up = (((base + i) & k) == 0);
            unsigned long long x = sk[i], y = sk[l];
            if (up ? (x < y) : (x > y)) { sk[i] = y; sk[l] = x; }
            __syncthreads();
        }
    }
    g[tid] = sk[tid]; g[tid+1024] = sk[tid+1024];
}

__global__ void __launch_bounds__(1024)
bitonic_local_finish(unsigned long long* __restrict__ keys, int k)
{
    __shared__ unsigned long long sk[2048];
    int chunk = blockIdx.x, b = blockIdx.y;
    unsigned long long* g = keys + (size_t)b*NSORT + (size_t)chunk*2048;
    int base = chunk*2048;
    int tid = threadIdx.x;
    sk[tid] = g[tid]; sk[tid+1024] = g[tid+1024];
    __syncthreads();
    for (int j = 1024; j >= 1; j >>= 1) {
        int i = ((tid & ~(j-1)) << 1) | (tid & (j-1));
        int l = i + j;
        bool up = (((base + i) & k) == 0);
        unsigned long long x = sk[i], y = sk[l];
        if (up ? (x < y) : (x > y)) { sk[i] = y; sk[l] = x; }
        __syncthreads();
    }
    g[tid] = sk[tid]; g[tid+1024] = sk[tid+1024];
}

__global__ void __launch_bounds__(256)
bitonic_global(unsigned long long* __restrict__ keys, int k, int j)
{
    int t = blockIdx.x*blockDim.x + threadIdx.x;   // [0, 32768) pairs
    int b = blockIdx.y;
    unsigned long long* g = keys + (size_t)b*NSORT;
    int i = ((t & ~(j-1)) << 1) | (t & (j-1));
    int l = i + j;
    bool up = ((i & k) == 0);
    unsigned long long x = g[i], y = g[l];
    if (up ? (x < y) : (x > y)) { g[i] = y; g[l] = x; }
}

// ---------------- extract top-2048 per batch ----------------
__global__ void extract_topk(const unsigned long long* __restrict__ keys,
                             const float* __restrict__ boxes,
                             float* __restrict__ selbox, float* __restrict__ selval,
                             int* __restrict__ sellab, int* __restrict__ Mv)
{
    int t = blockIdx.x*blockDim.x + threadIdx.x;
    if (t >= NBATCH*PRENMS) return;
    int b = t >> 11, r = t & (PRENMS-1);
    unsigned long long key = keys[(size_t)b*NSORT + r];
    unsigned int sb = (unsigned int)(key >> 32);
    unsigned int lo = (unsigned int)key;
    float4 bx = make_float4(0,0,0,0);
    int lab = 0; float val = 0.0f;
    if (sb > 0x80000000u) {   // score > 0 (i.e., passed threshold)
        unsigned int idx = 0xFFFFFFFFu - lo;
        int roi = idx / (NCLS-1);
        int cls = idx % (NCLS-1) + 1;
        const float* bp = boxes + ((size_t)b*NPROP + roi)*4;
        bx = make_float4(bp[0], bp[1], bp[2], bp[3]);
        lab = cls;
        val = __uint_as_float(sb & 0x7FFFFFFFu);
        atomicAdd(&Mv[b], 1);
    }
    ((float4*)selbox)[b*PRENMS + r] = bx;
    sellab[b*PRENMS + r] = lab;
    selval[b*PRENMS + r] = val;
}

// ---------------- greedy NMS + output packing (one block per batch) ----------------
__global__ void __launch_bounds__(1024)
nms_output(const float* __restrict__ selbox, const float* __restrict__ selval,
           const int* __restrict__ sellab, const int* __restrict__ Mv,
           float* __restrict__ out)
{
    int b = blockIdx.x;
    int tid = threadIdx.x;
    __shared__ float4 sbox[PRENMS];
    __shared__ int    slab[PRENMS];
    __shared__ unsigned char skeep[PRENMS];
    __shared__ int soutidx[NDETS];
    __shared__ int sK;
    int lim = Mv[b]; if (lim > PRENMS) lim = PRENMS;
    for (int r = tid; r < PRENMS; r += 1024) {
        sbox[r] = ((const float4*)selbox)[b*PRENMS + r];
        slab[r] = sellab[b*PRENMS + r];
        skeep[r] = (r < lim) ? 1 : 0;
    }
    __syncthreads();
    for (int i = 0; i < lim; i++) {
        if (skeep[i]) {
            float4 bi = sbox[i]; int li = slab[i];
            float areaI = (bi.z - bi.x)*(bi.w - bi.y);
            for (int j = i + 1 + tid; j < lim; j += 1024) {
                if (skeep[j] && slab[j] == li) {
                    float4 bj = sbox[j];
                    float ix = fminf(bi.z, bj.z) - fmaxf(bi.x, bj.x);
                    float iy = fminf(bi.w, bj.w) - fmaxf(bi.y, bj.y);
                    float inter = fmaxf(ix, 0.0f)*fmaxf(iy, 0.0f);
                    float areaJ = (bj.z - bj.x)*(bj.w - bj.y);
                    float iou = inter / (areaI + areaJ - inter + 1e-12f);
                    if (iou > 0.5f) skeep[j] = 0;
                }
            }
        }
        __syncthreads();
    }
    if (tid == 0) {
        int k = 0;
        for (int r = 0; r < lim && k < NDETS; r++)
            if (skeep[r]) soutidx[k++] = r;
        sK = k;
    }
    __syncthreads();
    if (tid < NDETS) {
        float x0=0, y0=0, x1=0, y1=0, sc=0, lb=0;
        if (tid < sK) {
            int r = soutidx[tid];
            float4 bb = sbox[r];
            x0 = bb.x; y0 = bb.y; x1 = bb.z; y1 = bb.w;
            sc = selval[b*PRENMS + r];
            lb = (float)slab[r];
        }
        float* ob = out + (size_t)b*NDETS*4 + tid*4;
        ob[0] = x0; ob[1] = y0; ob[2] = x1; ob[3] = y1;
        out[NBATCH*NDETS*4 + b*NDETS + tid] = sc;                 // scores at 800
        out[NBATCH*NDETS*4 + NBATCH*NDETS + b*NDETS + tid] = lb;  // labels at 1000
    }
}

// ---------------- host launch ----------------
extern "C" void kernel_launch(void* const* d_in, const int* in_sizes, int n_in,
                              void* d_out, int out_size)
{
    const float* features  = (const float*)d_in[0];
    const float* proposals = (const float*)d_in[1];
    const float* W1 = (const float*)d_in[2];
    const float* b1 = (const float*)d_in[3];
    const float* W2 = (const float*)d_in[4];
    const float* b2 = (const float*)d_in[5];
    const float* Wc = (const float*)d_in[6];
    const float* bc = (const float*)d_in[7];
    const float* Wr = (const float*)d_in[8];
    const float* br = (const float*)d_in[9];
    float* out = (float*)d_out;

    // resolve scratch symbol addresses (pure address queries; graph-safe)
    float *pX, *pH1, *pH2, *pLg, *pPr, *pDl, *pCur, *pSelB, *pSelV;
    unsigned long long* pKeys; int *pSelL, *pMv;
    cudaGetSymbolAddress((void**)&pX,   g_X);
    cudaGetSymbolAddress((void**)&pH1,  g_H1);
    cudaGetSymbolAddress((void**)&pH2,  g_H2);
    cudaGetSymbolAddress((void**)&pLg,  g_logits);
    cudaGetSymbolAddress((void**)&pPr,  g_probs);
    cudaGetSymbolAddress((void**)&pDl,  g_deltas);
    cudaGetSymbolAddress((void**)&pCur, g_cur);
    cudaGetSymbolAddress((void**)&pKeys,g_keys);
    cudaGetSymbolAddress((void**)&pSelB,g_selbox);
    cudaGetSymbolAddress((void**)&pSelV,g_selval);
    cudaGetSymbolAddress((void**)&pSelL,g_sellab);
    cudaGetSymbolAddress((void**)&pMv,  g_Mv);

    // zero output (covers any layout padding in d_out)
    zero_out_kernel<<<(out_size + 255)/256, 256>>>(out, out_size);

    // cur = proposals
    copy_kernel<<<(NROI*4 + 255)/256, 256>>>(proposals, pCur, NROI*4);

    const float stds[3][4] = {
        {0.1f, 0.1f, 0.2f, 0.2f},
        {0.05f, 0.05f, 0.1f, 0.1f},
        {0.033f, 0.033f, 0.067f, 0.067f}
    };

    for (int s = 0; s < 3; s++) {
        roi_align_kernel<<<NROI, 512>>>(features, pCur, pX);

        dim3 g1(FCDIM/BN, NROI/BM);   // (16, 8) = 128 blocks
        sgemm_f32x2<<<g1, 256>>>(pX,  W1 + (size_t)s*INDIM*FCDIM, b1 + s*FCDIM,
                                 pH1, NROI, FCDIM, INDIM, 1);
        sgemm_f32x2<<<g1, 256>>>(pH1, W2 + (size_t)s*FCDIM*FCDIM, b2 + s*FCDIM,
                                 pH2, NROI, FCDIM, FCDIM, 1);
        if (s == 2)
            gemm_logits<<<NROI/4, 128>>>(pH2, Wc + (size_t)s*FCDIM*NCLS, bc + s*NCLS, pLg);

        gemm_deltas<<<NROI/16, 64>>>(pH2, Wr + (size_t)s*FCDIM*4, br + s*4, pDl);
        decode_kernel<<<(NROI + 255)/256, 256>>>(pCur, pDl,
                                                 stds[s][0], stds[s][1], stds[s][2], stds[s][3]);
    }

    softmax81<<<NROI, 128>>>(pLg, pPr);
    build_keys<<<(NBATCH*NSORT + 255)/256, 256>>>(pPr, pCur, pKeys, pMv);

    // bitonic sort, descending, 65536 per batch
    dim3 gl(NSORT/2048, NBATCH);      // (32, 2) local blocks
    dim3 gg(NSORT/2/256, NBATCH);     // (128, 2) global step blocks
    bitonic_local_full<<<gl, 1024>>>(pKeys);
    for (int k = 4096; k <= NSORT; k <<= 1) {
        for (int j = k >> 1; j >= 2048; j >>= 1)
            bitonic_global<<<gg, 256>>>(pKeys, k, j);
        bitonic_local_finish<<<gl, 1024>>>(pKeys, k);
    }

    extract_topk<<<(NBATCH*PRENMS + 255)/256, 256>>>(pKeys, pCur, pSelB, pSelV, pSelL, pMv);
    nms_output<<<NBATCH, 1024>>>(pSelB, pSelV, pSelL, pMv, out);
}

// round 4
// speedup vs baseline: 1.2281x; 1.1587x over previous
#include <cuda_runtime.h>
#include <math.h>
#include <stdint.h>

// ---------------- problem constants ----------------
#define NBATCH   2
#define NPROP    512
#define NROI     1024            // B * N_PROP
#define CFEAT    256
#define FHW      200
#define PLANE    (FHW*FHW)       // 40000
#define POOLN    7
#define INDIM    (CFEAT*POOLN*POOLN)  // 12544
#define FCDIM    1024
#define NCLS     81
#define NSC      (NPROP*(NCLS-1))    // 40960 per batch
#define NSORT    65536
#define PRENMS   2048
#define NDETS    100
#define CLIPV    4.1351666f      // log(1000/16) rounded to f32
#define KSPLIT   4

typedef unsigned long long ull;

// ---------------- scratch (device globals; no runtime allocs) ----------------
__device__ float g_X[NROI*INDIM];        // pooled features, 51.4MB
__device__ float g_part[KSPLIT*NROI*FCDIM];  // split-K partials, 16MB
__device__ float g_H1[NROI*FCDIM];
__device__ float g_H2[NROI*FCDIM];
__device__ float g_logits[NROI*NCLS];
__device__ float g_probs[NROI*NCLS];
__device__ float g_deltas[NROI*4];
__device__ float g_cur[NROI*4];
__device__ unsigned long long g_keys[NBATCH*NSORT];
__device__ float g_selbox[NBATCH*PRENMS*4];
__device__ float g_selval[NBATCH*PRENMS];
__device__ int   g_sellab[NBATCH*PRENMS];
__device__ int   g_Mv[NBATCH];

// ---------------- f32x2 packed helpers (sm_100a) ----------------
__device__ __forceinline__ ull pack2(float x, float y) {
    ull r;
    asm("mov.b64 %0, {%1, %2};" : "=l"(r) : "f"(x), "f"(y));
    return r;
}
__device__ __forceinline__ void fma2(ull& d, ull a, ull b) {
    asm("fma.rn.f32x2 %0, %1, %2, %0;" : "+l"(d) : "l"(a), "l"(b));
}
__device__ __forceinline__ float2 unpack2(ull v) {
    float2 r;
    asm("mov.b64 {%0, %1}, %2;" : "=f"(r.x), "=f"(r.y) : "l"(v));
    return r;
}

// ---------------- utility kernels ----------------
__global__ void zero_out_kernel(float* out, int n) {
    int i = blockIdx.x*blockDim.x + threadIdx.x;
    if (i < n) out[i] = 0.0f;
}
__global__ void copy_kernel(const float* __restrict__ src, float* __restrict__ dst, int n) {
    int i = blockIdx.x*blockDim.x + threadIdx.x;
    if (i < n) dst[i] = src[i];
}

// ---------------- RoI align ----------------
__global__ void roi_align_kernel(const float* __restrict__ feat,
                                 const float* __restrict__ boxes,
                                 float* __restrict__ X)
{
    int r = blockIdx.x;
    int tid = threadIdx.x;
    __shared__ int   soff[4][196];
    __shared__ float sw  [4][196];
    if (tid < 196) {
        float x1 = boxes[r*4+0]*0.25f, y1 = boxes[r*4+1]*0.25f;
        float x2 = boxes[r*4+2]*0.25f, y2 = boxes[r*4+3]*0.25f;
        float bw = fmaxf(x2-x1, 1.0f) * (1.0f/7.0f);
        float bh = fmaxf(y2-y1, 1.0f) * (1.0f/7.0f);
        int cell = tid >> 2, s = tid & 3;
        int py = cell / 7, px = cell % 7;
        float sy = 0.25f + 0.5f*(float)(s >> 1);
        float sx = 0.25f + 0.5f*(float)(s & 1);
        float y = y1 + ((float)py + sy)*bh;
        float x = x1 + ((float)px + sx)*bw;
        float valid = (y > -1.0f && y < 200.0f && x > -1.0f && x < 200.0f) ? 1.0f : 0.0f;
        y = fminf(fmaxf(y, 0.0f), 199.0f);
        x = fminf(fmaxf(x, 0.0f), 199.0f);
        int y0 = (int)floorf(y), x0 = (int)floorf(x);
        int y1i = min(y0+1, 199), x1i = min(x0+1, 199);
        float ly = y - (float)y0, lx = x - (float)x0;
        float hy = 1.0f - ly, hx = 1.0f - lx;
        soff[0][tid] = y0 *FHW + x0;  sw[0][tid] = hy*hx*valid;
        soff[1][tid] = y0 *FHW + x1i; sw[1][tid] = hy*lx*valid;
        soff[2][tid] = y1i*FHW + x0;  sw[2][tid] = ly*hx*valid;
        soff[3][tid] = y1i*FHW + x1i; sw[3][tid] = ly*lx*valid;
    }
    __syncthreads();
    int b = r >> 9;
    const float* fb = feat + (size_t)b*CFEAT*PLANE;
    float* xr = X + (size_t)r*INDIM;
    for (int flat = tid; flat < INDIM; flat += blockDim.x) {
        int c = flat / 49, cell = flat % 49;
        const float* fp = fb + (size_t)c*PLANE;
        float acc = 0.0f;
        #pragma unroll
        for (int s = 0; s < 4; s++) {
            int e = cell*4 + s;
            acc += sw[0][e]*fp[soff[0][e]] + sw[1][e]*fp[soff[1][e]]
                 + sw[2][e]*fp[soff[2][e]] + sw[3][e]*fp[soff[3][e]];
        }
        xr[flat] = acc * 0.25f;
    }
}

// ---------------- 128x64x16 split-K SGEMM with f32x2 ----------------
// part[z][M,N] = A[M, z-th K slice] @ B[z-th K slice, N]
#define BM 128
#define BN 64
#define BK 16

__global__ void __launch_bounds__(256)
sgemm_f32x2_split(const float* __restrict__ A, const float* __restrict__ Bw,
                  float* __restrict__ part, int M, int N, int K)
{
    __shared__ __align__(16) float As[2][BK][BM];
    __shared__ __align__(16) float Bs[2][BK][BN];

    int tid = threadIdx.x;
    int bm = blockIdx.y * BM, bn = blockIdx.x * BN;
    int ks = blockIdx.z;
    int klen = K / KSPLIT;
    int kof = ks * klen;

    int tx = tid & 15, ty = tid >> 4;
    int m0 = ty << 3;
    int n0 = tx << 2;

    int arow = tid >> 2;
    int akq  = (tid & 3) << 2;
    int brow = tid >> 4;
    int bcol = (tid & 15) << 2;

    const float* Ap = A + (size_t)bm * K + kof;
    const float* Bp = Bw + (size_t)kof * N + bn;

    ull acc[4][4];
    #pragma unroll
    for (int i = 0; i < 4; i++)
        #pragma unroll
        for (int j = 0; j < 4; j++) acc[i][j] = 0ull;

    int nK = klen / BK;

    float4 ra0 = *(const float4*)(Ap + (size_t)arow*K + akq);
    float4 ra1 = *(const float4*)(Ap + (size_t)(arow+64)*K + akq);
    float4 rb  = *(const float4*)(Bp + (size_t)brow*N + bcol);
    As[0][akq+0][arow] = ra0.x; As[0][akq+1][arow] = ra0.y;
    As[0][akq+2][arow] = ra0.z; As[0][akq+3][arow] = ra0.w;
    As[0][akq+0][arow+64] = ra1.x; As[0][akq+1][arow+64] = ra1.y;
    As[0][akq+2][arow+64] = ra1.z; As[0][akq+3][arow+64] = ra1.w;
    *(float4*)&Bs[0][brow][bcol] = rb;
    __syncthreads();

    int buf = 0;
    for (int kb = 0; kb < nK; kb++) {
        if (kb + 1 < nK) {
            int k0 = (kb + 1) * BK;
            ra0 = *(const float4*)(Ap + (size_t)arow*K + k0 + akq);
            ra1 = *(const float4*)(Ap + (size_t)(arow+64)*K + k0 + akq);
            rb  = *(const float4*)(Bp + (size_t)(k0 + brow)*N + bcol);
        }
        #pragma unroll
        for (int k = 0; k < BK; k++) {
            float4 af0 = *(const float4*)&As[buf][k][m0];
            float4 af1 = *(const float4*)&As[buf][k][m0+4];
            ull a2[4];
            a2[0] = ((const ull*)&af0)[0];
            a2[1] = ((const ull*)&af0)[1];
            a2[2] = ((const ull*)&af1)[0];
            a2[3] = ((const ull*)&af1)[1];
            float4 bf = *(const float4*)&Bs[buf][k][n0];
            ull b2[4];
            b2[0] = pack2(bf.x, bf.x);
            b2[1] = pack2(bf.y, bf.y);
            b2[2] = pack2(bf.z, bf.z);
            b2[3] = pack2(bf.w, bf.w);
            #pragma unroll
            for (int i = 0; i < 4; i++) {
                fma2(acc[i][0], a2[i], b2[0]);
                fma2(acc[i][1], a2[i], b2[1]);
                fma2(acc[i][2], a2[i], b2[2]);
                fma2(acc[i][3], a2[i], b2[3]);
            }
        }
        if (kb + 1 < nK) {
            int nb = buf ^ 1;
            As[nb][akq+0][arow] = ra0.x; As[nb][akq+1][arow] = ra0.y;
            As[nb][akq+2][arow] = ra0.z; As[nb][akq+3][arow] = ra0.w;
            As[nb][akq+0][arow+64] = ra1.x; As[nb][akq+1][arow+64] = ra1.y;
            As[nb][akq+2][arow+64] = ra1.z; As[nb][akq+3][arow+64] = ra1.w;
            *(float4*)&Bs[nb][brow][bcol] = rb;
        }
        __syncthreads();
        buf ^= 1;
    }

    // write partials (no bias/relu here)
    float* Pp = part + (size_t)ks * M * N;
    #pragma unroll
    for (int i = 0; i < 4; i++) {
        float2 u0 = unpack2(acc[i][0]);
        float2 u1 = unpack2(acc[i][1]);
        float2 u2 = unpack2(acc[i][2]);
        float2 u3 = unpack2(acc[i][3]);
        float4 v0 = make_float4(u0.x, u1.x, u2.x, u3.x);
        float4 v1 = make_float4(u0.y, u1.y, u2.y, u3.y);
        int row0 = bm + m0 + 2*i;
        *(float4*)(Pp + (size_t)row0*N + bn + n0)     = v0;
        *(float4*)(Pp + (size_t)(row0+1)*N + bn + n0) = v1;
    }
}

// ---------------- split-K reduce: C = opt_relu(sum_s part[s] + bias) ----------------
__global__ void __launch_bounds__(256)
reduce_bias_relu(const float* __restrict__ part, const float* __restrict__ bias,
                 float* __restrict__ C, int M, int N, int doRelu)
{
    int i = blockIdx.x*blockDim.x + threadIdx.x;   // float4 index
    int total = (M*N) >> 2;
    if (i >= total) return;
    size_t stride = (size_t)M*N >> 2;
    const float4* p = (const float4*)part;
    float4 v0 = p[i];
    float4 v1 = p[i + stride];
    float4 v2 = p[i + 2*stride];
    float4 v3 = p[i + 3*stride];
    int col4 = (i << 2) & (N - 1);          // N is power of two (1024)
    float4 b4 = *(const float4*)(bias + col4);
    float4 r;
    r.x = ((v0.x + v1.x) + (v2.x + v3.x)) + b4.x;
    r.y = ((v0.y + v1.y) + (v2.y + v3.y)) + b4.y;
    r.z = ((v0.z + v1.z) + (v2.z + v3.z)) + b4.z;
    r.w = ((v0.w + v1.w) + (v2.w + v3.w)) + b4.w;
    if (doRelu) {
        r.x = fmaxf(r.x, 0.f); r.y = fmaxf(r.y, 0.f);
        r.z = fmaxf(r.z, 0.f); r.w = fmaxf(r.w, 0.f);
    }
    ((float4*)C)[i] = r;
}

// ---------------- logits head: [1024,1024] @ [1024,81] + bc ----------------
__global__ void __launch_bounds__(128)
gemm_logits(const float* __restrict__ H, const float* __restrict__ Wc,
            const float* __restrict__ bc, float* __restrict__ out)
{
    __shared__ float hs[4*1024];
    int m0 = blockIdx.x * 4;
    int t = threadIdx.x;
    const float4* src = (const float4*)(H + (size_t)m0*FCDIM);
    float4* dst = (float4*)hs;
    #pragma unroll
    for (int q = 0; q < 8; q++) dst[q*128 + t] = src[q*128 + t];
    __syncthreads();
    if (t < NCLS) {
        float a0=0, a1=0, a2=0, a3=0;
        for (int k = 0; k < FCDIM; k++) {
            float wv = Wc[k*NCLS + t];
            a0 += hs[k]*wv; a1 += hs[1024+k]*wv; a2 += hs[2048+k]*wv; a3 += hs[3072+k]*wv;
        }
        float bb = bc[t];
        out[(m0+0)*NCLS + t] = a0 + bb;
        out[(m0+1)*NCLS + t] = a1 + bb;
        out[(m0+2)*NCLS + t] = a2 + bb;
        out[(m0+3)*NCLS + t] = a3 + bb;
    }
}

// ---------------- delta head ----------------
__global__ void __launch_bounds__(64)
gemm_deltas(const float* __restrict__ H, const float* __restrict__ Wr,
            const float* __restrict__ br, float* __restrict__ out)
{
    int t = threadIdx.x;
    int m0 = blockIdx.x * 16;
    int r = t >> 2, n = t & 3;
    int row = m0 + r;
    const float* hp = H + (size_t)row*FCDIM;
    float a0=0, a1=0, a2=0, a3=0;
    for (int k = 0; k < FCDIM; k += 4) {
        a0 += hp[k+0]*Wr[(k+0)*4+n];
        a1 += hp[k+1]*Wr[(k+1)*4+n];
        a2 += hp[k+2]*Wr[(k+2)*4+n];
        a3 += hp[k+3]*Wr[(k+3)*4+n];
    }
    out[row*4+n] = (a0+a1)+(a2+a3) + br[n];
}

// ---------------- box decode ----------------
__global__ void decode_kernel(float* __restrict__ cur, const float* __restrict__ deltas,
                              float wx, float wy, float ww, float wh)
{
    int i = blockIdx.x*blockDim.x + threadIdx.x;
    if (i >= NROI) return;
    float px1 = cur[i*4+0], py1 = cur[i*4+1], px2 = cur[i*4+2], py2 = cur[i*4+3];
    float pw = fmaxf(px2 - px1, 1e-6f);
    float ph = fmaxf(py2 - py1, 1e-6f);
    float px = px1 + 0.5f*pw, py = py1 + 0.5f*ph;
    float dx = deltas[i*4+0]*wx, dy = deltas[i*4+1]*wy;
    float dw = fminf(deltas[i*4+2]*ww, CLIPV);
    float dh = fminf(deltas[i*4+3]*wh, CLIPV);
    float gx = dx*pw + px, gy = dy*ph + py;
    float gw = expf(dw)*pw, gh = expf(dh)*ph;
    cur[i*4+0] = fminf(fmaxf(gx - 0.5f*gw, 0.0f), 800.0f);
    cur[i*4+1] = fminf(fmaxf(gy - 0.5f*gh, 0.0f), 800.0f);
    cur[i*4+2] = fminf(fmaxf(gx + 0.5f*gw, 0.0f), 800.0f);
    cur[i*4+3] = fminf(fmaxf(gy + 0.5f*gh, 0.0f), 800.0f);
}

// ---------------- softmax over 81 classes ----------------
__global__ void __launch_bounds__(128)
softmax81(const float* __restrict__ logits, float* __restrict__ probs)
{
    int m = blockIdx.x, t = threadIdx.x;
    __shared__ float red[128];
    float v = (t < NCLS) ? logits[m*NCLS + t] : -3.0e38f;
    red[t] = v; __syncthreads();
    for (int s = 64; s > 0; s >>= 1) { if (t < s) red[t] = fmaxf(red[t], red[t+s]); __syncthreads(); }
    float mx = red[0];
    __syncthreads();
    float e = (t < NCLS) ? expf(v - mx) : 0.0f;
    red[t] = e; __syncthreads();
    for (int s = 64; s > 0; s >>= 1) { if (t < s) red[t] += red[t+s]; __syncthreads(); }
    float sum = red[0];
    if (t < NCLS) probs[m*NCLS + t] = e / sum;
}

// ---------------- sort keys ----------------
__global__ void build_keys(const float* __restrict__ probs, const float* __restrict__ boxes,
                           unsigned long long* __restrict__ keys, int* __restrict__ Mv)
{
    int t = blockIdx.x*blockDim.x + threadIdx.x;
    if (t == 0) { Mv[0] = 0; Mv[1] = 0; }
    if (t >= NBATCH*NSORT) return;
    int b = t >> 16, i = t & (NSORT-1);
    unsigned long long key = 0ull;
    if (i < NSC) {
        int roi = i / (NCLS-1);
        int cls = (i % (NCLS-1)) + 1;
        const float* bp = boxes + ((size_t)b*NPROP + roi)*4;
        float ws = bp[2] - bp[0], hs = bp[3] - bp[1];
        float fg = probs[((size_t)b*NPROP + roi)*NCLS + cls];
        unsigned int sb;
        if (fg > 0.05f && ws >= 1.0f && hs >= 1.0f) {
            sb = __float_as_uint(fg) | 0x80000000u;
        } else {
            sb = 0x407FFFFFu;
        }
        key = ((unsigned long long)sb << 32) | (unsigned long long)(0xFFFFFFFFu - (unsigned int)i);
    }
    keys[t] = key;
}

// ---------------- bitonic sort (descending), n=65536 per batch ----------------
__global__ void __launch_bounds__(1024)
bitonic_local_full(unsigned long long* __restrict__ keys)
{
    __shared__ unsigned long long sk[2048];
    int chunk = blockIdx.x, b = blockIdx.y;
    unsigned long long* g = keys + (size_t)b*NSORT + (size_t)chunk*2048;
    int base = chunk*2048;
    int tid = threadIdx.x;
    sk[tid] = g[tid]; sk[tid+1024] = g[tid+1024];
    __syncthreads();
    for (int k = 2; k <= 2048; k <<= 1) {
        for (int j = k >> 1; j >= 1; j >>= 1) {
            int i = ((tid & ~(j-1)) << 1) | (tid & (j-1));
            int l = i + j;
            bool up = (((base + i) & k) == 0);
            unsigned long long x = sk[i], y = sk[l];
            if (up ? (x < y) : (x > y)) { sk[i] = y; sk[l] = x; }
            __syncthreads();
        }
    }
    g[tid] = sk[tid]; g[tid+1024] = sk[tid+1024];
}

__global__ void __launch_bounds__(1024)
bitonic_local_finish(unsigned long long* __restrict__ keys, int k)
{
    __shared__ unsigned long long sk[2048];
    int chunk = blockIdx.x, b = blockIdx.y;
    unsigned long long* g = keys + (size_t)b*NSORT + (size_t)chunk*2048;
    int base = chunk*2048;
    int tid = threadIdx.x;
    sk[tid] = g[tid]; sk[tid+1024] = g[tid+1024];
    __syncthreads();
    for (int j = 1024; j >= 1; j >>= 1) {
        int i = ((tid & ~(j-1)) << 1) | (tid & (j-1));
        int l = i + j;
        bool up = (((base + i) & k) == 0);
        unsigned long long x = sk[i], y = sk[l];
        if (up ? (x < y) : (x > y)) { sk[i] = y; sk[l] = x; }
        __syncthreads();
    }
    g[tid] = sk[tid]; g[tid+1024] = sk[tid+1024];
}

__global__ void __launch_bounds__(256)
bitonic_global(unsigned long long* __restrict__ keys, int k, int j)
{
    int t = blockIdx.x*blockDim.x + threadIdx.x;
    int b = blockIdx.y;
    unsigned long long* g = keys + (size_t)b*NSORT;
    int i = ((t & ~(j-1)) << 1) | (t & (j-1));
    int l = i + j;
    bool up = ((i & k) == 0);
    unsigned long long x = g[i], y = g[l];
    if (up ? (x < y) : (x > y)) { g[i] = y; g[l] = x; }
}

// ---------------- extract top-2048 per batch ----------------
__global__ void extract_topk(const unsigned long long* __restrict__ keys,
                             const float* __restrict__ boxes,
                             float* __restrict__ selbox, float* __restrict__ selval,
                             int* __restrict__ sellab, int* __restrict__ Mv)
{
    int t = blockIdx.x*blockDim.x + threadIdx.x;
    if (t >= NBATCH*PRENMS) return;
    int b = t >> 11, r = t & (PRENMS-1);
    unsigned long long key = keys[(size_t)b*NSORT + r];
    unsigned int sb = (unsigned int)(key >> 32);
    unsigned int lo = (unsigned int)key;
    float4 bx = make_float4(0,0,0,0);
    int lab = 0; float val = 0.0f;
    if (sb > 0x80000000u) {
        unsigned int idx = 0xFFFFFFFFu - lo;
        int roi = idx / (NCLS-1);
        int cls = idx % (NCLS-1) + 1;
        const float* bp = boxes + ((size_t)b*NPROP + roi)*4;
        bx = make_float4(bp[0], bp[1], bp[2], bp[3]);
        lab = cls;
        val = __uint_as_float(sb & 0x7FFFFFFFu);
        atomicAdd(&Mv[b], 1);
    }
    ((float4*)selbox)[b*PRENMS + r] = bx;
    sellab[b*PRENMS + r] = lab;
    selval[b*PRENMS + r] = val;
}

// ---------------- greedy NMS + output packing ----------------
__global__ void __launch_bounds__(1024)
nms_output(const float* __restrict__ selbox, const float* __restrict__ selval,
           const int* __restrict__ sellab, const int* __restrict__ Mv,
           float* __restrict__ out)
{
    int b = blockIdx.x;
    int tid = threadIdx.x;
    __shared__ float4 sbox[PRENMS];
    __shared__ int    slab[PRENMS];
    __shared__ unsigned char skeep[PRENMS];
    __shared__ int soutidx[NDETS];
    __shared__ int sK;
    int lim = Mv[b]; if (lim > PRENMS) lim = PRENMS;
    for (int r = tid; r < PRENMS; r += 1024) {
        sbox[r] = ((const float4*)selbox)[b*PRENMS + r];
        slab[r] = sellab[b*PRENMS + r];
        skeep[r] = (r < lim) ? 1 : 0;
    }
    __syncthreads();
    for (int i = 0; i < lim; i++) {
        if (skeep[i]) {
            float4 bi = sbox[i]; int li = slab[i];
            float areaI = (bi.z - bi.x)*(bi.w - bi.y);
            for (int j = i + 1 + tid; j < lim; j += 1024) {
                if (skeep[j] && slab[j] == li) {
                    float4 bj = sbox[j];
                    float ix = fminf(bi.z, bj.z) - fmaxf(bi.x, bj.x);
                    float iy = fminf(bi.w, bj.w) - fmaxf(bi.y, bj.y);
                    float inter = fmaxf(ix, 0.0f)*fmaxf(iy, 0.0f);
                    float areaJ = (bj.z - bj.x)*(bj.w - bj.y);
                    float iou = inter / (areaI + areaJ - inter + 1e-12f);
                    if (iou > 0.5f) skeep[j] = 0;
                }
            }
        }
        __syncthreads();
    }
    if (tid == 0) {
        int k = 0;
        for (int r = 0; r < lim && k < NDETS; r++)
            if (skeep[r]) soutidx[k++] = r;
        sK = k;
    }
    __syncthreads();
    if (tid < NDETS) {
        float x0=0, y0=0, x1=0, y1=0, sc=0, lb=0;
        if (tid < sK) {
            int r = soutidx[tid];
            float4 bb = sbox[r];
            x0 = bb.x; y0 = bb.y; x1 = bb.z; y1 = bb.w;
            sc = selval[b*PRENMS + r];
            lb = (float)slab[r];
        }
        float* ob = out + (size_t)b*NDETS*4 + tid*4;
        ob[0] = x0; ob[1] = y0; ob[2] = x1; ob[3] = y1;
        out[NBATCH*NDETS*4 + b*NDETS + tid] = sc;
        out[NBATCH*NDETS*4 + NBATCH*NDETS + b*NDETS + tid] = lb;
    }
}

// ---------------- host launch ----------------
extern "C" void kernel_launch(void* const* d_in, const int* in_sizes, int n_in,
                              void* d_out, int out_size)
{
    const float* features  = (const float*)d_in[0];
    const float* proposals = (const float*)d_in[1];
    const float* W1 = (const float*)d_in[2];
    const float* b1 = (const float*)d_in[3];
    const float* W2 = (const float*)d_in[4];
    const float* b2 = (const float*)d_in[5];
    const float* Wc = (const float*)d_in[6];
    const float* bc = (const float*)d_in[7];
    const float* Wr = (const float*)d_in[8];
    const float* br = (const float*)d_in[9];
    float* out = (float*)d_out;

    float *pX, *pPart, *pH1, *pH2, *pLg, *pPr, *pDl, *pCur, *pSelB, *pSelV;
    unsigned long long* pKeys; int *pSelL, *pMv;
    cudaGetSymbolAddress((void**)&pX,   g_X);
    cudaGetSymbolAddress((void**)&pPart,g_part);
    cudaGetSymbolAddress((void**)&pH1,  g_H1);
    cudaGetSymbolAddress((void**)&pH2,  g_H2);
    cudaGetSymbolAddress((void**)&pLg,  g_logits);
    cudaGetSymbolAddress((void**)&pPr,  g_probs);
    cudaGetSymbolAddress((void**)&pDl,  g_deltas);
    cudaGetSymbolAddress((void**)&pCur, g_cur);
    cudaGetSymbolAddress((void**)&pKeys,g_keys);
    cudaGetSymbolAddress((void**)&pSelB,g_selbox);
    cudaGetSymbolAddress((void**)&pSelV,g_selval);
    cudaGetSymbolAddress((void**)&pSelL,g_sellab);
    cudaGetSymbolAddress((void**)&pMv,  g_Mv);

    zero_out_kernel<<<(out_size + 255)/256, 256>>>(out, out_size);
    copy_kernel<<<(NROI*4 + 255)/256, 256>>>(proposals, pCur, NROI*4);

    const float stds[3][4] = {
        {0.1f, 0.1f, 0.2f, 0.2f},
        {0.05f, 0.05f, 0.1f, 0.1f},
        {0.033f, 0.033f, 0.067f, 0.067f}
    };

    dim3 gg1(FCDIM/BN, NROI/BM, KSPLIT);   // (16, 8, 4) = 512 blocks
    int redBlocks = (NROI*FCDIM/4 + 255)/256;

    for (int s = 0; s < 3; s++) {
        roi_align_kernel<<<NROI, 512>>>(features, pCur, pX);

        sgemm_f32x2_split<<<gg1, 256>>>(pX, W1 + (size_t)s*INDIM*FCDIM, pPart,
                                        NROI, FCDIM, INDIM);
        reduce_bias_relu<<<redBlocks, 256>>>(pPart, b1 + s*FCDIM, pH1, NROI, FCDIM, 1);

        sgemm_f32x2_split<<<gg1, 256>>>(pH1, W2 + (size_t)s*FCDIM*FCDIM, pPart,
                                        NROI, FCDIM, FCDIM);
        reduce_bias_relu<<<redBlocks, 256>>>(pPart, b2 + s*FCDIM, pH2, NROI, FCDIM, 1);

        if (s == 2)
            gemm_logits<<<NROI/4, 128>>>(pH2, Wc + (size_t)s*FCDIM*NCLS, bc + s*NCLS, pLg);

        gemm_deltas<<<NROI/16, 64>>>(pH2, Wr + (size_t)s*FCDIM*4, br + s*4, pDl);
        decode_kernel<<<(NROI + 255)/256, 256>>>(pCur, pDl,
                                                 stds[s][0], stds[s][1], stds[s][2], stds[s][3]);
    }

    softmax81<<<NROI, 128>>>(pLg, pPr);
    build_keys<<<(NBATCH*NSORT + 255)/256, 256>>>(pPr, pCur, pKeys, pMv);

    dim3 gl(NSORT/2048, NBATCH);
    dim3 gg(NSORT/2/256, NBATCH);
    bitonic_local_full<<<gl, 1024>>>(pKeys);
    for (int k = 4096; k <= NSORT; k <<= 1) {
        for (int j = k >> 1; j >= 2048; j >>= 1)
            bitonic_global<<<gg, 256>>>(pKeys, k, j);
        bitonic_local_finish<<<gl, 1024>>>(pKeys, k);
    }

    extract_topk<<<(NBATCH*PRENMS + 255)/256, 256>>>(pKeys, pCur, pSelB, pSelV, pSelL, pMv);
    nms_output<<<NBATCH, 1024>>>(pSelB, pSelV, pSelL, pMv, out);
}

// round 5
// speedup vs baseline: 1.2982x; 1.0570x over previous
#include <cuda_runtime.h>
#include <math.h>
#include <stdint.h>

// ---------------- problem constants ----------------
#define NBATCH   2
#define NPROP    512
#define NROI     1024            // B * N_PROP
#define CFEAT    256
#define FHW      200
#define PLANE    (FHW*FHW)       // 40000
#define POOLN    7
#define INDIM    (CFEAT*POOLN*POOLN)  // 12544
#define FCDIM    1024
#define NCLS     81
#define NSC      (NPROP*(NCLS-1))    // 40960 per batch
#define NSORT    65536
#define PRENMS   2048
#define NDETS    100
#define CLIPV    4.1351666f      // log(1000/16) rounded to f32
#define KSPLIT   8

typedef unsigned long long ull;

// ---------------- scratch (device globals; no runtime allocs) ----------------
__device__ float g_X[NROI*INDIM];            // pooled features, 51.4MB
__device__ float g_part[KSPLIT*NROI*FCDIM];  // split-K partials, 32MB
__device__ float g_H1[NROI*FCDIM];
__device__ float g_H2[NROI*FCDIM];
__device__ float g_logits[NROI*NCLS];
__device__ float g_probs[NROI*NCLS];
__device__ float g_deltas[NROI*4];
__device__ float g_cur[NROI*4];
__device__ unsigned long long g_keys[NBATCH*NSORT];
__device__ float g_selbox[NBATCH*PRENMS*4];
__device__ float g_selval[NBATCH*PRENMS];
__device__ int   g_sellab[NBATCH*PRENMS];
__device__ int   g_Mv[NBATCH];

// ---------------- f32x2 packed helpers (sm_100a) ----------------
__device__ __forceinline__ ull pack2(float x, float y) {
    ull r;
    asm("mov.b64 %0, {%1, %2};" : "=l"(r) : "f"(x), "f"(y));
    return r;
}
__device__ __forceinline__ void fma2(ull& d, ull a, ull b) {
    asm("fma.rn.f32x2 %0, %1, %2, %0;" : "+l"(d) : "l"(a), "l"(b));
}
__device__ __forceinline__ float2 unpack2(ull v) {
    float2 r;
    asm("mov.b64 {%0, %1}, %2;" : "=f"(r.x), "=f"(r.y) : "l"(v));
    return r;
}

// ---------------- utility kernels ----------------
__global__ void zero_out_kernel(float* out, int n) {
    int i = blockIdx.x*blockDim.x + threadIdx.x;
    if (i < n) out[i] = 0.0f;
}
__global__ void copy_kernel(const float* __restrict__ src, float* __restrict__ dst, int n) {
    int i = blockIdx.x*blockDim.x + threadIdx.x;
    if (i < n) dst[i] = src[i];
}

// ---------------- RoI align ----------------
__global__ void roi_align_kernel(const float* __restrict__ feat,
                                 const float* __restrict__ boxes,
                                 float* __restrict__ X)
{
    int r = blockIdx.x;
    int tid = threadIdx.x;
    __shared__ int   soff[4][196];
    __shared__ float sw  [4][196];
    if (tid < 196) {
        float x1 = boxes[r*4+0]*0.25f, y1 = boxes[r*4+1]*0.25f;
        float x2 = boxes[r*4+2]*0.25f, y2 = boxes[r*4+3]*0.25f;
        float bw = fmaxf(x2-x1, 1.0f) * (1.0f/7.0f);
        float bh = fmaxf(y2-y1, 1.0f) * (1.0f/7.0f);
        int cell = tid >> 2, s = tid & 3;
        int py = cell / 7, px = cell % 7;
        float sy = 0.25f + 0.5f*(float)(s >> 1);
        float sx = 0.25f + 0.5f*(float)(s & 1);
        float y = y1 + ((float)py + sy)*bh;
        float x = x1 + ((float)px + sx)*bw;
        float valid = (y > -1.0f && y < 200.0f && x > -1.0f && x < 200.0f) ? 1.0f : 0.0f;
        y = fminf(fmaxf(y, 0.0f), 199.0f);
        x = fminf(fmaxf(x, 0.0f), 199.0f);
        int y0 = (int)floorf(y), x0 = (int)floorf(x);
        int y1i = min(y0+1, 199), x1i = min(x0+1, 199);
        float ly = y - (float)y0, lx = x - (float)x0;
        float hy = 1.0f - ly, hx = 1.0f - lx;
        soff[0][tid] = y0 *FHW + x0;  sw[0][tid] = hy*hx*valid;
        soff[1][tid] = y0 *FHW + x1i; sw[1][tid] = hy*lx*valid;
        soff[2][tid] = y1i*FHW + x0;  sw[2][tid] = ly*hx*valid;
        soff[3][tid] = y1i*FHW + x1i; sw[3][tid] = ly*lx*valid;
    }
    __syncthreads();
    int b = r >> 9;
    const float* fb = feat + (size_t)b*CFEAT*PLANE;
    float* xr = X + (size_t)r*INDIM;
    for (int flat = tid; flat < INDIM; flat += blockDim.x) {
        int c = flat / 49, cell = flat % 49;
        const float* fp = fb + (size_t)c*PLANE;
        float acc = 0.0f;
        #pragma unroll
        for (int s = 0; s < 4; s++) {
            int e = cell*4 + s;
            acc += sw[0][e]*fp[soff[0][e]] + sw[1][e]*fp[soff[1][e]]
                 + sw[2][e]*fp[soff[2][e]] + sw[3][e]*fp[soff[3][e]];
        }
        xr[flat] = acc * 0.25f;
    }
}

// ---------------- 128x128x16 split-K SGEMM with f32x2 ----------------
// part[z][M,N] = A[M, z-th K slice] @ B[z-th K slice, N]
// 256 threads, per-thread 8(M)x8(N); smem/fma balanced at 64B per 32 fma2.
#define BM 128
#define BN 128
#define BK 16

__global__ void __launch_bounds__(256, 2)
sgemm_f32x2_split(const float* __restrict__ A, const float* __restrict__ Bw,
                  float* __restrict__ part, int M, int N, int K)
{
    __shared__ __align__(16) float As[2][BK][BM];
    __shared__ __align__(16) float Bs[2][BK][BN];

    int tid = threadIdx.x;
    int bm = blockIdx.y * BM, bn = blockIdx.x * BN;
    int ks = blockIdx.z;
    int klen = K / KSPLIT;
    int kof = ks * klen;

    int tx = tid & 15, ty = tid >> 4;
    int m0 = ty << 3;          // 0..120
    int n0 = tx << 3;          // 0..120

    // A load mapping: thread -> row (tid>>1), 8 consecutive k at ((tid&1)*8)
    int arow = tid >> 1;
    int akq  = (tid & 1) << 3;
    // B load mapping: thread -> row (tid>>4), 8 consecutive n at ((tid&15)*8)
    int brow = tid >> 4;
    int bcol = (tid & 15) << 3;

    const float* Ap = A + (size_t)bm * K + kof;
    const float* Bp = Bw + (size_t)kof * N + bn;

    ull acc[4][8];
    #pragma unroll
    for (int i = 0; i < 4; i++)
        #pragma unroll
        for (int j = 0; j < 8; j++) acc[i][j] = 0ull;

    int nK = klen / BK;

    float4 ra0, ra1, rb0, rb1;
    ra0 = *(const float4*)(Ap + (size_t)arow*K + akq);
    ra1 = *(const float4*)(Ap + (size_t)arow*K + akq + 4);
    rb0 = *(const float4*)(Bp + (size_t)brow*N + bcol);
    rb1 = *(const float4*)(Bp + (size_t)brow*N + bcol + 4);
    As[0][akq+0][arow] = ra0.x; As[0][akq+1][arow] = ra0.y;
    As[0][akq+2][arow] = ra0.z; As[0][akq+3][arow] = ra0.w;
    As[0][akq+4][arow] = ra1.x; As[0][akq+5][arow] = ra1.y;
    As[0][akq+6][arow] = ra1.z; As[0][akq+7][arow] = ra1.w;
    *(float4*)&Bs[0][brow][bcol]   = rb0;
    *(float4*)&Bs[0][brow][bcol+4] = rb1;
    __syncthreads();

    int buf = 0;
    for (int kb = 0; kb < nK; kb++) {
        if (kb + 1 < nK) {
            int k0 = (kb + 1) * BK;
            ra0 = *(const float4*)(Ap + (size_t)arow*K + k0 + akq);
            ra1 = *(const float4*)(Ap + (size_t)arow*K + k0 + akq + 4);
            rb0 = *(const float4*)(Bp + (size_t)(k0 + brow)*N + bcol);
            rb1 = *(const float4*)(Bp + (size_t)(k0 + brow)*N + bcol + 4);
        }
        #pragma unroll
        for (int k = 0; k < BK; k++) {
            float4 af0 = *(const float4*)&As[buf][k][m0];
            float4 af1 = *(const float4*)&As[buf][k][m0+4];
            ull a2[4];
            a2[0] = ((const ull*)&af0)[0];
            a2[1] = ((const ull*)&af0)[1];
            a2[2] = ((const ull*)&af1)[0];
            a2[3] = ((const ull*)&af1)[1];
            float4 bf0 = *(const float4*)&Bs[buf][k][n0];
            float4 bf1 = *(const float4*)&Bs[buf][k][n0+4];
            ull b2[8];
            b2[0] = pack2(bf0.x, bf0.x); b2[1] = pack2(bf0.y, bf0.y);
            b2[2] = pack2(bf0.z, bf0.z); b2[3] = pack2(bf0.w, bf0.w);
            b2[4] = pack2(bf1.x, bf1.x); b2[5] = pack2(bf1.y, bf1.y);
            b2[6] = pack2(bf1.z, bf1.z); b2[7] = pack2(bf1.w, bf1.w);
            #pragma unroll
            for (int i = 0; i < 4; i++) {
                #pragma unroll
                for (int j = 0; j < 8; j++)
                    fma2(acc[i][j], a2[i], b2[j]);
            }
        }
        if (kb + 1 < nK) {
            int nb = buf ^ 1;
            As[nb][akq+0][arow] = ra0.x; As[nb][akq+1][arow] = ra0.y;
            As[nb][akq+2][arow] = ra0.z; As[nb][akq+3][arow] = ra0.w;
            As[nb][akq+4][arow] = ra1.x; As[nb][akq+5][arow] = ra1.y;
            As[nb][akq+6][arow] = ra1.z; As[nb][akq+7][arow] = ra1.w;
            *(float4*)&Bs[nb][brow][bcol]   = rb0;
            *(float4*)&Bs[nb][brow][bcol+4] = rb1;
        }
        __syncthreads();
        buf ^= 1;
    }

    // write partials
    float* Pp = part + (size_t)ks * M * N;
    #pragma unroll
    for (int i = 0; i < 4; i++) {
        float2 u[8];
        #pragma unroll
        for (int j = 0; j < 8; j++) u[j] = unpack2(acc[i][j]);
        float4 e0 = make_float4(u[0].x, u[1].x, u[2].x, u[3].x);
        float4 e1 = make_float4(u[4].x, u[5].x, u[6].x, u[7].x);
        float4 o0 = make_float4(u[0].y, u[1].y, u[2].y, u[3].y);
        float4 o1 = make_float4(u[4].y, u[5].y, u[6].y, u[7].y);
        int row0 = bm + m0 + 2*i;
        float* p0 = Pp + (size_t)row0*N + bn + n0;
        float* p1 = Pp + (size_t)(row0+1)*N + bn + n0;
        *(float4*)(p0)     = e0;
        *(float4*)(p0 + 4) = e1;
        *(float4*)(p1)     = o0;
        *(float4*)(p1 + 4) = o1;
    }
}

// ---------------- split-K reduce: C = opt_relu(sum_s part[s] + bias) ----------------
__global__ void __launch_bounds__(256)
reduce_bias_relu(const float* __restrict__ part, const float* __restrict__ bias,
                 float* __restrict__ C, int M, int N, int doRelu)
{
    int i = blockIdx.x*blockDim.x + threadIdx.x;   // float4 index
    int total = (M*N) >> 2;
    if (i >= total) return;
    size_t stride = (size_t)M*N >> 2;
    const float4* p = (const float4*)part;
    float4 v[KSPLIT];
    #pragma unroll
    for (int s = 0; s < KSPLIT; s++) v[s] = p[i + s*stride];
    int col4 = (i << 2) & (N - 1);          // N power of two (1024)
    float4 b4 = *(const float4*)(bias + col4);
    float4 r;
    r.x = (((v[0].x+v[1].x)+(v[2].x+v[3].x)) + ((v[4].x+v[5].x)+(v[6].x+v[7].x))) + b4.x;
    r.y = (((v[0].y+v[1].y)+(v[2].y+v[3].y)) + ((v[4].y+v[5].y)+(v[6].y+v[7].y))) + b4.y;
    r.z = (((v[0].z+v[1].z)+(v[2].z+v[3].z)) + ((v[4].z+v[5].z)+(v[6].z+v[7].z))) + b4.z;
    r.w = (((v[0].w+v[1].w)+(v[2].w+v[3].w)) + ((v[4].w+v[5].w)+(v[6].w+v[7].w))) + b4.w;
    if (doRelu) {
        r.x = fmaxf(r.x, 0.f); r.y = fmaxf(r.y, 0.f);
        r.z = fmaxf(r.z, 0.f); r.w = fmaxf(r.w, 0.f);
    }
    ((float4*)C)[i] = r;
}

// ---------------- logits head: [1024,1024] @ [1024,81] + bc ----------------
__global__ void __launch_bounds__(128)
gemm_logits(const float* __restrict__ H, const float* __restrict__ Wc,
            const float* __restrict__ bc, float* __restrict__ out)
{
    __shared__ float hs[4*1024];
    int m0 = blockIdx.x * 4;
    int t = threadIdx.x;
    const float4* src = (const float4*)(H + (size_t)m0*FCDIM);
    float4* dst = (float4*)hs;
    #pragma unroll
    for (int q = 0; q < 8; q++) dst[q*128 + t] = src[q*128 + t];
    __syncthreads();
    if (t < NCLS) {
        float a0=0, a1=0, a2=0, a3=0;
        for (int k = 0; k < FCDIM; k++) {
            float wv = Wc[k*NCLS + t];
            a0 += hs[k]*wv; a1 += hs[1024+k]*wv; a2 += hs[2048+k]*wv; a3 += hs[3072+k]*wv;
        }
        float bb = bc[t];
        out[(m0+0)*NCLS + t] = a0 + bb;
        out[(m0+1)*NCLS + t] = a1 + bb;
        out[(m0+2)*NCLS + t] = a2 + bb;
        out[(m0+3)*NCLS + t] = a3 + bb;
    }
}

// ---------------- delta head ----------------
__global__ void __launch_bounds__(64)
gemm_deltas(const float* __restrict__ H, const float* __restrict__ Wr,
            const float* __restrict__ br, float* __restrict__ out)
{
    int t = threadIdx.x;
    int m0 = blockIdx.x * 16;
    int r = t >> 2, n = t & 3;
    int row = m0 + r;
    const float* hp = H + (size_t)row*FCDIM;
    float a0=0, a1=0, a2=0, a3=0;
    for (int k = 0; k < FCDIM; k += 4) {
        a0 += hp[k+0]*Wr[(k+0)*4+n];
        a1 += hp[k+1]*Wr[(k+1)*4+n];
        a2 += hp[k+2]*Wr[(k+2)*4+n];
        a3 += hp[k+3]*Wr[(k+3)*4+n];
    }
    out[row*4+n] = (a0+a1)+(a2+a3) + br[n];
}

// ---------------- box decode ----------------
__global__ void decode_kernel(float* __restrict__ cur, const float* __restrict__ deltas,
                              float wx, float wy, float ww, float wh)
{
    int i = blockIdx.x*blockDim.x + threadIdx.x;
    if (i >= NROI) return;
    float px1 = cur[i*4+0], py1 = cur[i*4+1], px2 = cur[i*4+2], py2 = cur[i*4+3];
    float pw = fmaxf(px2 - px1, 1e-6f);
    float ph = fmaxf(py2 - py1, 1e-6f);
    float px = px1 + 0.5f*pw, py = py1 + 0.5f*ph;
    float dx = deltas[i*4+0]*wx, dy = deltas[i*4+1]*wy;
    float dw = fminf(deltas[i*4+2]*ww, CLIPV);
    float dh = fminf(deltas[i*4+3]*wh, CLIPV);
    float gx = dx*pw + px, gy = dy*ph + py;
    float gw = expf(dw)*pw, gh = expf(dh)*ph;
    cur[i*4+0] = fminf(fmaxf(gx - 0.5f*gw, 0.0f), 800.0f);
    cur[i*4+1] = fminf(fmaxf(gy - 0.5f*gh, 0.0f), 800.0f);
    cur[i*4+2] = fminf(fmaxf(gx + 0.5f*gw, 0.0f), 800.0f);
    cur[i*4+3] = fminf(fmaxf(gy + 0.5f*gh, 0.0f), 800.0f);
}

// ---------------- softmax over 81 classes ----------------
__global__ void __launch_bounds__(128)
softmax81(const float* __restrict__ logits, float* __restrict__ probs)
{
    int m = blockIdx.x, t = threadIdx.x;
    __shared__ float red[128];
    float v = (t < NCLS) ? logits[m*NCLS + t] : -3.0e38f;
    red[t] = v; __syncthreads();
    for (int s = 64; s > 0; s >>= 1) { if (t < s) red[t] = fmaxf(red[t], red[t+s]); __syncthreads(); }
    float mx = red[0];
    __syncthreads();
    float e = (t < NCLS) ? expf(v - mx) : 0.0f;
    red[t] = e; __syncthreads();
    for (int s = 64; s > 0; s >>= 1) { if (t < s) red[t] += red[t+s]; __syncthreads(); }
    float sum = red[0];
    if (t < NCLS) probs[m*NCLS + t] = e / sum;
}

// ---------------- sort keys ----------------
__global__ void build_keys(const float* __restrict__ probs, const float* __restrict__ boxes,
                           unsigned long long* __restrict__ keys, int* __restrict__ Mv)
{
    int t = blockIdx.x*blockDim.x + threadIdx.x;
    if (t == 0) { Mv[0] = 0; Mv[1] = 0; }
    if (t >= NBATCH*NSORT) return;
    int b = t >> 16, i = t & (NSORT-1);
    unsigned long long key = 0ull;
    if (i < NSC) {
        int roi = i / (NCLS-1);
        int cls = (i % (NCLS-1)) + 1;
        const float* bp = boxes + ((size_t)b*NPROP + roi)*4;
        float ws = bp[2] - bp[0], hs = bp[3] - bp[1];
        float fg = probs[((size_t)b*NPROP + roi)*NCLS + cls];
        unsigned int sb;
        if (fg > 0.05f && ws >= 1.0f && hs >= 1.0f) {
            sb = __float_as_uint(fg) | 0x80000000u;
        } else {
            sb = 0x407FFFFFu;
        }
        key = ((unsigned long long)sb << 32) | (unsigned long long)(0xFFFFFFFFu - (unsigned int)i);
    }
    keys[t] = key;
}

// ---------------- bitonic sort (descending), n=65536 per batch ----------------
__global__ void __launch_bounds__(1024)
bitonic_local_full(unsigned long long* __restrict__ keys)
{
    __shared__ unsigned long long sk[2048];
    int chunk = blockIdx.x, b = blockIdx.y;
    unsigned long long* g = keys + (size_t)b*NSORT + (size_t)chunk*2048;
    int base = chunk*2048;
    int tid = threadIdx.x;
    sk[tid] = g[tid]; sk[tid+1024] = g[tid+1024];
    __syncthreads();
    for (int k = 2; k <= 2048; k <<= 1) {
        for (int j = k >> 1; j >= 1; j >>= 1) {
            int i = ((tid & ~(j-1)) << 1) | (tid & (j-1));
            int l = i + j;
            bool up = (((base + i) & k) == 0);
            unsigned long long x = sk[i], y = sk[l];
            if (up ? (x < y) : (x > y)) { sk[i] = y; sk[l] = x; }
            __syncthreads();
        }
    }
    g[tid] = sk[tid]; g[tid+1024] = sk[tid+1024];
}

__global__ void __launch_bounds__(1024)
bitonic_local_finish(unsigned long long* __restrict__ keys, int k)
{
    __shared__ unsigned long long sk[2048];
    int chunk = blockIdx.x, b = blockIdx.y;
    unsigned long long* g = keys + (size_t)b*NSORT + (size_t)chunk*2048;
    int base = chunk*2048;
    int tid = threadIdx.x;
    sk[tid] = g[tid]; sk[tid+1024] = g[tid+1024];
    __syncthreads();
    for (int j = 1024; j >= 1; j >>= 1) {
        int i = ((tid & ~(j-1)) << 1) | (tid & (j-1));
        int l = i + j;
        bool up = (((base + i) & k) == 0);
        unsigned long long x = sk[i], y = sk[l];
        if (up ? (x < y) : (x > y)) { sk[i] = y; sk[l] = x; }
        __syncthreads();
    }
    g[tid] = sk[tid]; g[tid+1024] = sk[tid+1024];
}

__global__ void __launch_bounds__(256)
bitonic_global(unsigned long long* __restrict__ keys, int k, int j)
{
    int t = blockIdx.x*blockDim.x + threadIdx.x;
    int b = blockIdx.y;
    unsigned long long* g = keys + (size_t)b*NSORT;
    int i = ((t & ~(j-1)) << 1) | (t & (j-1));
    int l = i + j;
    bool up = ((i & k) == 0);
    unsigned long long x = g[i], y = g[l];
    if (up ? (x < y) : (x > y)) { g[i] = y; g[l] = x; }
}

// ---------------- extract top-2048 per batch ----------------
__global__ void extract_topk(const unsigned long long* __restrict__ keys,
                             const float* __restrict__ boxes,
                             float* __restrict__ selbox, float* __restrict__ selval,
                             int* __restrict__ sellab, int* __restrict__ Mv)
{
    int t = blockIdx.x*blockDim.x + threadIdx.x;
    if (t >= NBATCH*PRENMS) return;
    int b = t >> 11, r = t & (PRENMS-1);
    unsigned long long key = keys[(size_t)b*NSORT + r];
    unsigned int sb = (unsigned int)(key >> 32);
    unsigned int lo = (unsigned int)key;
    float4 bx = make_float4(0,0,0,0);
    int lab = 0; float val = 0.0f;
    if (sb > 0x80000000u) {
        unsigned int idx = 0xFFFFFFFFu - lo;
        int roi = idx / (NCLS-1);
        int cls = idx % (NCLS-1) + 1;
        const float* bp = boxes + ((size_t)b*NPROP + roi)*4;
        bx = make_float4(bp[0], bp[1], bp[2], bp[3]);
        lab = cls;
        val = __uint_as_float(sb & 0x7FFFFFFFu);
        atomicAdd(&Mv[b], 1);
    }
    ((float4*)selbox)[b*PRENMS + r] = bx;
    sellab[b*PRENMS + r] = lab;
    selval[b*PRENMS + r] = val;
}

// ---------------- greedy NMS + output packing ----------------
__global__ void __launch_bounds__(1024)
nms_output(const float* __restrict__ selbox, const float* __restrict__ selval,
           const int* __restrict__ sellab, const int* __restrict__ Mv,
           float* __restrict__ out)
{
    int b = blockIdx.x;
    int tid = threadIdx.x;
    __shared__ float4 sbox[PRENMS];
    __shared__ int    slab[PRENMS];
    __shared__ unsigned char skeep[PRENMS];
    __shared__ int soutidx[NDETS];
    __shared__ int sK;
    int lim = Mv[b]; if (lim > PRENMS) lim = PRENMS;
    for (int r = tid; r < PRENMS; r += 1024) {
        sbox[r] = ((const float4*)selbox)[b*PRENMS + r];
        slab[r] = sellab[b*PRENMS + r];
        skeep[r] = (r < lim) ? 1 : 0;
    }
    __syncthreads();
    int cnt = 0;   // kept boxes with index <= i (uniform across threads)
    for (int i = 0; i < lim; i++) {
        bool alive = (skeep[i] != 0);
        if (alive) {
            cnt++;
            float4 bi = sbox[i]; int li = slab[i];
            float areaI = (bi.z - bi.x)*(bi.w - bi.y);
            for (int j = i + 1 + tid; j < lim; j += 1024) {
                if (skeep[j] && slab[j] == li) {
                    float4 bj = sbox[j];
                    float ix = fminf(bi.z, bj.z) - fmaxf(bi.x, bj.x);
                    float iy = fminf(bi.w, bj.w) - fmaxf(bi.y, bj.y);
                    float inter = fmaxf(ix, 0.0f)*fmaxf(iy, 0.0f);
                    float areaJ = (bj.z - bj.x)*(bj.w - bj.y);
                    float iou = inter / (areaI + areaJ - inter + 1e-12f);
                    if (iou > 0.5f) skeep[j] = 0;
                }
            }
        }
        __syncthreads();
        // first NDETS kept (by index) are final once cnt reaches NDETS:
        // later suppressions only affect j > i, which can't enter the output.
        if (cnt >= NDETS) break;
    }
    if (tid == 0) {
        int k = 0;
        for (int r = 0; r < lim && k < NDETS; r++)
            if (skeep[r]) soutidx[k++] = r;
        sK = k;
    }
    __syncthreads();
    if (tid < NDETS) {
        float x0=0, y0=0, x1=0, y1=0, sc=0, lb=0;
        if (tid < sK) {
            int r = soutidx[tid];
            float4 bb = sbox[r];
            x0 = bb.x; y0 = bb.y; x1 = bb.z; y1 = bb.w;
            sc = selval[b*PRENMS + r];
            lb = (float)slab[r];
        }
        float* ob = out + (size_t)b*NDETS*4 + tid*4;
        ob[0] = x0; ob[1] = y0; ob[2] = x1; ob[3] = y1;
        out[NBATCH*NDETS*4 + b*NDETS + tid] = sc;
        out[NBATCH*NDETS*4 + NBATCH*NDETS + b*NDETS + tid] = lb;
    }
}

// ---------------- host launch ----------------
extern "C" void kernel_launch(void* const* d_in, const int* in_sizes, int n_in,
                              void* d_out, int out_size)
{
    const float* features  = (const float*)d_in[0];
    const float* proposals = (const float*)d_in[1];
    const float* W1 = (const float*)d_in[2];
    const float* b1 = (const float*)d_in[3];
    const float* W2 = (const float*)d_in[4];
    const float* b2 = (const float*)d_in[5];
    const float* Wc = (const float*)d_in[6];
    const float* bc = (const float*)d_in[7];
    const float* Wr = (const float*)d_in[8];
    const float* br = (const float*)d_in[9];
    float* out = (float*)d_out;

    float *pX, *pPart, *pH1, *pH2, *pLg, *pPr, *pDl, *pCur, *pSelB, *pSelV;
    unsigned long long* pKeys; int *pSelL, *pMv;
    cudaGetSymbolAddress((void**)&pX,   g_X);
    cudaGetSymbolAddress((void**)&pPart,g_part);
    cudaGetSymbolAddress((void**)&pH1,  g_H1);
    cudaGetSymbolAddress((void**)&pH2,  g_H2);
    cudaGetSymbolAddress((void**)&pLg,  g_logits);
    cudaGetSymbolAddress((void**)&pPr,  g_probs);
    cudaGetSymbolAddress((void**)&pDl,  g_deltas);
    cudaGetSymbolAddress((void**)&pCur, g_cur);
    cudaGetSymbolAddress((void**)&pKeys,g_keys);
    cudaGetSymbolAddress((void**)&pSelB,g_selbox);
    cudaGetSymbolAddress((void**)&pSelV,g_selval);
    cudaGetSymbolAddress((void**)&pSelL,g_sellab);
    cudaGetSymbolAddress((void**)&pMv,  g_Mv);

    zero_out_kernel<<<(out_size + 255)/256, 256>>>(out, out_size);
    copy_kernel<<<(NROI*4 + 255)/256, 256>>>(proposals, pCur, NROI*4);

    const float stds[3][4] = {
        {0.1f, 0.1f, 0.2f, 0.2f},
        {0.05f, 0.05f, 0.1f, 0.1f},
        {0.033f, 0.033f, 0.067f, 0.067f}
    };

    dim3 gg1(FCDIM/BN, NROI/BM, KSPLIT);   // (8, 8, 8) = 512 blocks
    int redBlocks = (NROI*FCDIM/4 + 255)/256;

    for (int s = 0; s < 3; s++) {
        roi_align_kernel<<<NROI, 512>>>(features, pCur, pX);

        sgemm_f32x2_split<<<gg1, 256>>>(pX, W1 + (size_t)s*INDIM*FCDIM, pPart,
                                        NROI, FCDIM, INDIM);
        reduce_bias_relu<<<redBlocks, 256>>>(pPart, b1 + s*FCDIM, pH1, NROI, FCDIM, 1);

        sgemm_f32x2_split<<<gg1, 256>>>(pH1, W2 + (size_t)s*FCDIM*FCDIM, pPart,
                                        NROI, FCDIM, FCDIM);
        reduce_bias_relu<<<redBlocks, 256>>>(pPart, b2 + s*FCDIM, pH2, NROI, FCDIM, 1);

        if (s == 2)
            gemm_logits<<<NROI/4, 128>>>(pH2, Wc + (size_t)s*FCDIM*NCLS, bc + s*NCLS, pLg);

        gemm_deltas<<<NROI/16, 64>>>(pH2, Wr + (size_t)s*FCDIM*4, br + s*4, pDl);
        decode_kernel<<<(NROI + 255)/256, 256>>>(pCur, pDl,
                                                 stds[s][0], stds[s][1], stds[s][2], stds[s][3]);
    }

    softmax81<<<NROI, 128>>>(pLg, pPr);
    build_keys<<<(NBATCH*NSORT + 255)/256, 256>>>(pPr, pCur, pKeys, pMv);

    dim3 gl(NSORT/2048, NBATCH);
    dim3 gg(NSORT/2/256, NBATCH);
    bitonic_local_full<<<gl, 1024>>>(pKeys);
    for (int k = 4096; k <= NSORT; k <<= 1) {
        for (int j = k >> 1; j >= 2048; j >>= 1)
            bitonic_global<<<gg, 256>>>(pKeys, k, j);
        bitonic_local_finish<<<gl, 1024>>>(pKeys, k);
    }

    extract_topk<<<(NBATCH*PRENMS + 255)/256, 256>>>(pKeys, pCur, pSelB, pSelV, pSelL, pMv);
    nms_output<<<NBATCH, 1024>>>(pSelB, pSelV, pSelL, pMv, out);
}